// round 9
// baseline (speedup 1.0000x reference)
#include <cuda_runtime.h>
#include <cuda_fp16.h>
#include <math_constants.h>
#include <cstdint>

// Problem constants
constexpr int B  = 2;
constexpr int T  = 2048;
constexpr int E  = 1024;
constexpr int H  = 16;
constexpr int DH = 64;
constexpr int M    = B * T;        // 4096
constexpr int NQKV = 3 * H * DH;   // 3072
constexpr int HD   = H * DH;       // 1024

// Q pre-scale: DH^-0.5 * log2(e)  (attention uses exp2)
#define QSCALE 0.180336880972f

// ---------------------------------------------------------------------------
// fp16 m16n8k16 fragment layouts (PTX ISA):
// A (16x16) elem (r,c): lane=((r&7)<<2)|((c&7)>>1), reg=((c>>3)<<1)|((r>>3)&1), half=c&1
// B (16x8)  elem (k,n): lane=((n&7)<<2)|((k&7)>>1), reg=(k>>3)&1,               half=k&1
// C (16x8): c0=(gid,2t) c1=(gid,2t+1) c2=(gid+8,2t) c3=(gid+8,2t+1)
// ---------------------------------------------------------------------------
__device__ uint32_t g_Xf  [(size_t)(M / 16) * (E / 16) * 128];
__device__ uint32_t g_Wqf [(size_t)(NQKV / 8) * (E / 16) * 64];
__device__ uint32_t g_Wof [(size_t)(E / 8) * (HD / 16) * 64];
__device__ uint32_t g_Qf  [(size_t)(B * H) * (T / 16) * 4 * 128];
__device__ uint32_t g_Kf  [(size_t)(B * H) * (T / 8) * 4 * 64];
__device__ uint32_t g_Vf  [(size_t)(B * H) * (T / 16) * 8 * 64];
__device__ uint32_t g_AOf [(size_t)(M / 16) * (HD / 16) * 128];

// ---------------------------------------------------------------------------
// Helpers
// ---------------------------------------------------------------------------
__device__ __forceinline__ uint32_t f22h(float a, float b) {
    __half2 h = __floats2half2_rn(a, b);
    return *(uint32_t*)&h;
}
__device__ __forceinline__ float ex2(float x) {
    float y;
    asm("ex2.approx.f32 %0, %1;" : "=f"(y) : "f"(x));
    return y;
}
__device__ __forceinline__ uint32_t smem_u32(const void* p) {
    return (uint32_t)__cvta_generic_to_shared(p);
}
__device__ __forceinline__ void cpasync16(uint32_t dst, const void* src) {
    asm volatile("cp.async.cg.shared.global [%0], [%1], 16;" :: "r"(dst), "l"(src));
}
__device__ __forceinline__ void cp_commit() { asm volatile("cp.async.commit_group;"); }
template <int N>
__device__ __forceinline__ void cp_wait() { asm volatile("cp.async.wait_group %0;" :: "n"(N)); }

__device__ __forceinline__ void mma16(float* c, const uint32_t* a, const uint32_t* b) {
    asm volatile(
        "mma.sync.aligned.m16n8k16.row.col.f32.f16.f16.f32 "
        "{%0,%1,%2,%3}, {%4,%5,%6,%7}, {%8,%9}, {%0,%1,%2,%3};"
        : "+f"(c[0]), "+f"(c[1]), "+f"(c[2]), "+f"(c[3])
        : "r"(a[0]), "r"(a[1]), "r"(a[2]), "r"(a[3]), "r"(b[0]), "r"(b[1]));
}

// ---------------------------------------------------------------------------
// Pre-passes: fragment-ordered fp16 operands
// ---------------------------------------------------------------------------
__global__ __launch_bounds__(256) void k_permA(const float* __restrict__ X) {
    int idx  = blockIdx.x * 256 + threadIdx.x;
    int frag = idx >> 5, lane = idx & 31;
    int mt = frag >> 6, kt = frag & 63;
    int gid = lane >> 2, tp = lane & 3;
    int r0 = mt * 16 + gid, c0 = kt * 16 + tp * 2;
    float2 x00 = *(const float2*)&X[(size_t)r0 * E + c0];
    float2 x10 = *(const float2*)&X[(size_t)(r0 + 8) * E + c0];
    float2 x01 = *(const float2*)&X[(size_t)r0 * E + c0 + 8];
    float2 x11 = *(const float2*)&X[(size_t)(r0 + 8) * E + c0 + 8];
    *(uint4*)&g_Xf[(size_t)idx * 4] =
        make_uint4(f22h(x00.x, x00.y), f22h(x10.x, x10.y),
                   f22h(x01.x, x01.y), f22h(x11.x, x11.y));
}

__global__ __launch_bounds__(256) void k_permWq(const float* __restrict__ W) {
    int idx  = blockIdx.x * 256 + threadIdx.x;
    int frag = idx >> 5, lane = idx & 31;
    int nt = frag >> 6, kt = frag & 63;
    int np = nt * 8 + (lane >> 2);                  // permuted col [which|h|d]
    int which = np >> 10, h = (np >> 6) & 15, d = np & 63;
    int c = d * 48 + which * 16 + h;                // original col
    int k0 = kt * 16 + (lane & 3) * 2;
    uint2 v;
    v.x = f22h(W[(size_t)k0 * NQKV + c],       W[(size_t)(k0 + 1) * NQKV + c]);
    v.y = f22h(W[(size_t)(k0 + 8) * NQKV + c], W[(size_t)(k0 + 9) * NQKV + c]);
    *(uint2*)&g_Wqf[(size_t)idx * 2] = v;
}

__global__ __launch_bounds__(256) void k_permWo(const float* __restrict__ W) {
    int idx  = blockIdx.x * 256 + threadIdx.x;
    int frag = idx >> 5, lane = idx & 31;
    int nt = frag >> 6, kt = frag & 63;
    int n = nt * 8 + (lane >> 2);
    int k0 = kt * 16 + (lane & 3) * 2;
    uint2 v;
    v.x = f22h(W[(size_t)k0 * E + n],       W[(size_t)(k0 + 1) * E + n]);
    v.y = f22h(W[(size_t)(k0 + 8) * E + n], W[(size_t)(k0 + 9) * E + n]);
    *(uint2*)&g_Wof[(size_t)idx * 2] = v;
}

// ---------------------------------------------------------------------------
// GEMM core: 256x128 block, 8 warps (4m x 2n), warp tile 64x64.
// K-stage = 64 -> 16 stages; 3-stage cp.async; stage = A 32KB + B 16KB = 48KB.
// LDS per MAC halved vs 64x32 warp tile.
// ---------------------------------------------------------------------------
constexpr int GEMM_STAGE_W   = 12288;                   // words per stage
constexpr int GEMM_SMEM_BYTES = 3 * GEMM_STAGE_W * 4;   // 147456 B

template <int EPI>   // 0 = QKV scatter, 1 = direct float out
__device__ __forceinline__ void gemm_core(const uint32_t* __restrict__ Af,
                                          const uint32_t* __restrict__ Bf,
                                          float* __restrict__ Cout) {
    extern __shared__ uint32_t smem[];     // [3][12288]
    const int tid = threadIdx.x, lane = tid & 31, warp = tid >> 5;
    const int wm = warp >> 1, wn = warp & 1;
    const int bm = blockIdx.y * 256, bn = blockIdx.x * 128;
    const int gid = lane >> 2, tig = lane & 3;

    auto issue = [&](int s) {
        uint32_t base = smem_u32(&smem[(s % 3) * GEMM_STAGE_W]);
        int ktb = s * 4;
        // A: 32KB = 2048 chunks; frag f = ktl*16 + mtl (64 frags x 512B)
#pragma unroll
        for (int it = 0; it < 8; it++) {
            int c = it * 256 + tid;
            int f = c >> 5, off = c & 31;
            int mtl = f & 15, ktl = f >> 4;
            cpasync16(base + (f * 128 + off * 4) * 4,
                      &Af[((size_t)((bm >> 4) + mtl) * 64 + ktb + ktl) * 128 + off * 4]);
        }
        // B: 16KB = 1024 chunks; frag f = ktl*16 + ntl (64 frags x 256B)
#pragma unroll
        for (int it = 0; it < 4; it++) {
            int c = it * 256 + tid;
            int f = c >> 4, off = c & 15;
            int ntl = f & 15, ktl = f >> 4;
            cpasync16(base + 8192 * 4 + (f * 64 + off * 4) * 4,
                      &Bf[((size_t)((bn >> 3) + ntl) * 64 + ktb + ktl) * 64 + off * 4]);
        }
        cp_commit();
    };

    float acc[4][8][4] = {};
    constexpr int NS = 16;
    issue(0);
    issue(1);
    for (int s = 0; s < NS; s++) {
        if (s < NS - 1) cp_wait<1>();
        else            cp_wait<0>();
        __syncthreads();
        if (s + 2 < NS) issue(s + 2);
        const uint32_t* As = &smem[(s % 3) * GEMM_STAGE_W];
        const uint32_t* Bs = As + 8192;
#pragma unroll
        for (int ks = 0; ks < 4; ks++) {
            uint32_t af[4][4], bf[8][2];
#pragma unroll
            for (int i = 0; i < 4; i++)
                *(uint4*)af[i] = *(const uint4*)&As[((ks * 16 + wm * 4 + i) * 128) + lane * 4];
#pragma unroll
            for (int j = 0; j < 8; j++)
                *(uint2*)bf[j] = *(const uint2*)&Bs[((ks * 16 + wn * 8 + j) * 64) + lane * 2];
#pragma unroll
            for (int i = 0; i < 4; i++)
#pragma unroll
                for (int j = 0; j < 8; j++)
                    mma16(acc[i][j], af[i], bf[j]);
        }
    }

    if (EPI == 0) {
        // QKV scatter into attention fragment layouts (cols permuted [which|h|d])
        const int which = bn >> 10;
#pragma unroll
        for (int i = 0; i < 4; i++) {
#pragma unroll
            for (int j = 0; j < 8; j++) {
                int m0  = bm + (wm * 4 + i) * 16 + gid;       // rows m0, m0+8
                int b_  = m0 >> 11, t0 = m0 & (T - 1);
                int np0 = bn + (wn * 8 + j) * 8 + tig * 2;
                int h = (np0 >> 6) & 15, d0 = np0 & 63;
                const float* a = acc[i][j];
                if (which == 0) {
                    size_t fb = (((size_t)(b_ * H + h) * (T / 16) + (t0 >> 4)) * 4 +
                                 (d0 >> 4)) * 32 + lane;
                    int rb = ((d0 >> 3) & 1) * 2;
                    g_Qf[fb * 4 + rb]     = f22h(a[0] * QSCALE, a[1] * QSCALE);
                    g_Qf[fb * 4 + rb + 1] = f22h(a[2] * QSCALE, a[3] * QSCALE);
                } else if (which == 1) {
                    int rg = (d0 >> 3) & 1;
                    size_t f0 = (((size_t)(b_ * H + h) * (T / 8) + (t0 >> 3)) * 4 +
                                 (d0 >> 4)) * 32 + lane;
                    size_t f1 = (((size_t)(b_ * H + h) * (T / 8) + ((t0 + 8) >> 3)) * 4 +
                                 (d0 >> 4)) * 32 + lane;
                    g_Kf[f0 * 2 + rg] = f22h(a[0], a[1]);
                    g_Kf[f1 * 2 + rg] = f22h(a[2], a[3]);
                } else {
                    __half* Vh = (__half*)g_Vf;
#pragma unroll
                    for (int r = 0; r < 4; r++) {
                        int tt = t0 + (r >> 1) * 8;
                        int d  = d0 + (r & 1);
                        int lv = ((d & 7) << 2) | ((tt & 7) >> 1);
                        int rv = (tt & 15) >> 3;
                        size_t w = ((((size_t)(b_ * H + h) * (T / 16) + (tt >> 4)) * 8 +
                                     (d >> 3)) * 32 + lv) * 2 + rv;
                        Vh[w * 2 + (tt & 1)] = __float2half_rn(a[r]);
                    }
                }
            }
        }
    } else {
#pragma unroll
        for (int i = 0; i < 4; i++) {
#pragma unroll
            for (int j = 0; j < 8; j++) {
#pragma unroll
                for (int rh = 0; rh < 2; rh++) {
                    int m = bm + (wm * 4 + i) * 16 + gid + rh * 8;
                    int n = bn + (wn * 8 + j) * 8 + tig * 2;
                    *(float2*)&Cout[(size_t)m * E + n] =
                        make_float2(acc[i][j][rh * 2], acc[i][j][rh * 2 + 1]);
                }
            }
        }
    }
}

__global__ __launch_bounds__(256) void k_qkv() {
    gemm_core<0>(g_Xf, g_Wqf, nullptr);
}
__global__ __launch_bounds__(256) void k_out(float* __restrict__ Cout) {
    gemm_core<1>(g_AOf, g_Wof, Cout);
}

// ---------------------------------------------------------------------------
// Flash attention, no online max. BLOCK_M=128 via 4 warps x 32 q-rows each.
// Q A-frags in registers (2 mt x 4 kt); K/V B-frags shared, each load feeds
// 2x the MACs vs the 16-row version. 128 threads/CTA.
// ---------------------------------------------------------------------------
constexpr int ATTN_SMEM_BYTES = 2 * 4096 * 4;   // 32KB

__global__ __launch_bounds__(128) void k_attn() {
    extern __shared__ uint32_t sm[];
    const int tid = threadIdx.x, lane = tid & 31, warp = tid >> 5;
    const int bh = blockIdx.y;
    const int bm = blockIdx.x * 128;

    const uint32_t* __restrict__ Kfb = g_Kf + (size_t)bh * (T / 8) * 4 * 64;
    const uint32_t* __restrict__ Vfb = g_Vf + (size_t)bh * (T / 16) * 8 * 64;

    // Q fragments: 32 rows (2 mt tiles) x 64 d (4 kt tiles)
    uint32_t qf[2][4][4];
#pragma unroll
    for (int mt = 0; mt < 2; mt++) {
        const uint32_t* qsrc =
            g_Qf + ((size_t)bh * (T / 16) + (bm >> 4) + warp * 2 + mt) * 4 * 128;
#pragma unroll
        for (int dt = 0; dt < 4; dt++)
            *(uint4*)qf[mt][dt] = *(const uint4*)&qsrc[dt * 128 + lane * 4];
    }

    auto issue = [&](int s) {
        uint32_t sK = smem_u32(&sm[(s & 1) * 4096]);
        uint32_t sV = sK + 2048 * 4;
        int jb8 = s * 8, jb16 = s * 4;
#pragma unroll
        for (int it = 0; it < 4; it++) {   // K: 512 chunks
            int c = it * 128 + tid;
            int f = c >> 4, off = c & 15;
            cpasync16(sK + (f * 64 + off * 4) * 4,
                      &Kfb[((size_t)(jb8 + (f >> 2)) * 4 + (f & 3)) * 64 + off * 4]);
        }
#pragma unroll
        for (int it = 0; it < 4; it++) {   // V: 512 chunks
            int c = it * 128 + tid;
            int f = c >> 4, off = c & 15;
            cpasync16(sV + (f * 64 + off * 4) * 4,
                      &Vfb[((size_t)(jb16 + (f >> 3)) * 8 + (f & 7)) * 64 + off * 4]);
        }
        cp_commit();
    };

    float li[2][2] = {};
    float o[2][8][4] = {};

    constexpr int NS = T / 64;   // 32
    issue(0);
    for (int it = 0; it < NS; it++) {
        if (it + 1 < NS) { issue(it + 1); cp_wait<1>(); }
        else             { cp_wait<0>(); }
        __syncthreads();
        const uint32_t* Ks = &sm[(it & 1) * 4096];
        const uint32_t* Vs = Ks + 2048;

        // S = Q K^T : 32 x 64 per warp; each bf feeds both mt tiles
        float s[2][8][4] = {};
#pragma unroll
        for (int dt = 0; dt < 4; dt++) {
#pragma unroll
            for (int jt = 0; jt < 8; jt++) {
                uint32_t bf[2];
                *(uint2*)bf = *(const uint2*)&Ks[((jt * 4 + dt) * 64) + lane * 2];
                mma16(s[0][jt], qf[0][dt], bf);
                mma16(s[1][jt], qf[1][dt], bf);
            }
        }

        // P = exp2(S), accumulate row sums
#pragma unroll
        for (int mt = 0; mt < 2; mt++) {
#pragma unroll
            for (int jt = 0; jt < 8; jt++) {
#pragma unroll
                for (int r = 0; r < 4; r++)
                    s[mt][jt][r] = ex2(s[mt][jt][r]);
                li[mt][0] += s[mt][jt][0] + s[mt][jt][1];
                li[mt][1] += s[mt][jt][2] + s[mt][jt][3];
            }
        }

        // O += P V ; each V bf feeds both mt tiles
#pragma unroll
        for (int kt = 0; kt < 4; kt++) {
            uint32_t pf[2][4];
#pragma unroll
            for (int mt = 0; mt < 2; mt++) {
                pf[mt][0] = f22h(s[mt][2 * kt][0],     s[mt][2 * kt][1]);
                pf[mt][1] = f22h(s[mt][2 * kt][2],     s[mt][2 * kt][3]);
                pf[mt][2] = f22h(s[mt][2 * kt + 1][0], s[mt][2 * kt + 1][1]);
                pf[mt][3] = f22h(s[mt][2 * kt + 1][2], s[mt][2 * kt + 1][3]);
            }
#pragma unroll
            for (int dn = 0; dn < 8; dn++) {
                uint32_t bf[2];
                *(uint2*)bf = *(const uint2*)&Vs[((kt * 8 + dn) * 64) + lane * 2];
                mma16(o[0][dn], pf[0], bf);
                mma16(o[1][dn], pf[1], bf);
            }
        }
        __syncthreads();
    }

    // Quad-reduce row sums once, then epilogue: AO -> A-frags for k_out
    const int b_ = bh >> 4, h_ = bh & 15;
#pragma unroll
    for (int mt = 0; mt < 2; mt++) {
#pragma unroll
        for (int h = 0; h < 2; h++) {
            li[mt][h] += __shfl_xor_sync(0xffffffffu, li[mt][h], 1);
            li[mt][h] += __shfl_xor_sync(0xffffffffu, li[mt][h], 2);
        }
        float inv0 = 1.f / li[mt][0], inv1 = 1.f / li[mt][1];
        const int mtg = ((b_ * T + bm) >> 4) + warp * 2 + mt;
#pragma unroll
        for (int dn = 0; dn < 8; dn++) {
            int kt = h_ * 4 + (dn >> 1);
            int rb = (dn & 1) * 2;
            size_t fb = ((size_t)mtg * 64 + kt) * 32 + lane;
            g_AOf[fb * 4 + rb]     = f22h(o[mt][dn][0] * inv0, o[mt][dn][1] * inv0);
            g_AOf[fb * 4 + rb + 1] = f22h(o[mt][dn][2] * inv1, o[mt][dn][3] * inv1);
        }
    }
}

// ---------------------------------------------------------------------------
extern "C" void kernel_launch(void* const* d_in, const int* in_sizes, int n_in,
                              void* d_out, int out_size) {
    const float* x     = (const float*)d_in[0];
    const float* w_qkv = (const float*)d_in[1];
    const float* w_out = (const float*)d_in[2];
    float* out = (float*)d_out;

    cudaFuncSetAttribute(k_attn, cudaFuncAttributeMaxDynamicSharedMemorySize,
                         ATTN_SMEM_BYTES);
    cudaFuncSetAttribute(k_qkv, cudaFuncAttributeMaxDynamicSharedMemorySize,
                         GEMM_SMEM_BYTES);
    cudaFuncSetAttribute(k_out, cudaFuncAttributeMaxDynamicSharedMemorySize,
                         GEMM_SMEM_BYTES);

    // Pre-passes: fragment-ordered fp16 operands
    k_permA <<<(M / 16) * (E / 16) * 32 / 256, 256>>>(x);
    k_permWq<<<(NQKV / 8) * (E / 16) * 32 / 256, 256>>>(w_qkv);
    k_permWo<<<(E / 8) * (HD / 16) * 32 / 256, 256>>>(w_out);

    k_qkv<<<dim3(NQKV / 128, M / 256), 256, GEMM_SMEM_BYTES>>>();
    k_attn<<<dim3(T / 128, B * H), 128, ATTN_SMEM_BYTES>>>();
    k_out<<<dim3(E / 128, M / 256), 256, GEMM_SMEM_BYTES>>>(out);
}

// round 10
// speedup vs baseline: 1.0241x; 1.0241x over previous
#include <cuda_runtime.h>
#include <cuda_fp16.h>
#include <math_constants.h>
#include <cstdint>

// Problem constants
constexpr int B  = 2;
constexpr int T  = 2048;
constexpr int E  = 1024;
constexpr int H  = 16;
constexpr int DH = 64;
constexpr int M    = B * T;        // 4096
constexpr int NQKV = 3 * H * DH;   // 3072
constexpr int HD   = H * DH;       // 1024

// Q pre-scale: DH^-0.5 * log2(e)  (attention uses exp2)
#define QSCALE 0.180336880972f

// ---------------------------------------------------------------------------
// fp16 m16n8k16 fragment layouts (PTX ISA):
// A (16x16) elem (r,c): lane=((r&7)<<2)|((c&7)>>1), reg=((c>>3)<<1)|((r>>3)&1), half=c&1
// B (16x8)  elem (k,n): lane=((n&7)<<2)|((k&7)>>1), reg=(k>>3)&1,               half=k&1
// C (16x8): c0=(gid,2t) c1=(gid,2t+1) c2=(gid+8,2t) c3=(gid+8,2t+1)
// ---------------------------------------------------------------------------
__device__ uint32_t g_Xf  [(size_t)(M / 16) * (E / 16) * 128];
__device__ uint32_t g_Wqf [(size_t)(NQKV / 8) * (E / 16) * 64];
__device__ uint32_t g_Wof [(size_t)(E / 8) * (HD / 16) * 64];
__device__ uint32_t g_Qf  [(size_t)(B * H) * (T / 16) * 4 * 128];
__device__ uint32_t g_Kf  [(size_t)(B * H) * (T / 8) * 4 * 64];
__device__ uint32_t g_Vf  [(size_t)(B * H) * (T / 16) * 8 * 64];
__device__ uint32_t g_AOf [(size_t)(M / 16) * (HD / 16) * 128];

// ---------------------------------------------------------------------------
// Helpers
// ---------------------------------------------------------------------------
__device__ __forceinline__ uint32_t f22h(float a, float b) {
    __half2 h = __floats2half2_rn(a, b);
    return *(uint32_t*)&h;
}
__device__ __forceinline__ float ex2(float x) {
    float y;
    asm("ex2.approx.f32 %0, %1;" : "=f"(y) : "f"(x));
    return y;
}
__device__ __forceinline__ uint32_t smem_u32(const void* p) {
    return (uint32_t)__cvta_generic_to_shared(p);
}
__device__ __forceinline__ void cpasync16(uint32_t dst, const void* src) {
    asm volatile("cp.async.cg.shared.global [%0], [%1], 16;" :: "r"(dst), "l"(src));
}
__device__ __forceinline__ void cp_commit() { asm volatile("cp.async.commit_group;"); }
template <int N>
__device__ __forceinline__ void cp_wait() { asm volatile("cp.async.wait_group %0;" :: "n"(N)); }

__device__ __forceinline__ void mma16(float* c, const uint32_t* a, const uint32_t* b) {
    asm volatile(
        "mma.sync.aligned.m16n8k16.row.col.f32.f16.f16.f32 "
        "{%0,%1,%2,%3}, {%4,%5,%6,%7}, {%8,%9}, {%0,%1,%2,%3};"
        : "+f"(c[0]), "+f"(c[1]), "+f"(c[2]), "+f"(c[3])
        : "r"(a[0]), "r"(a[1]), "r"(a[2]), "r"(a[3]), "r"(b[0]), "r"(b[1]));
}

// ---------------------------------------------------------------------------
// Pre-passes: fragment-ordered fp16 operands
// ---------------------------------------------------------------------------
__global__ __launch_bounds__(256) void k_permA(const float* __restrict__ X) {
    int idx  = blockIdx.x * 256 + threadIdx.x;
    int frag = idx >> 5, lane = idx & 31;
    int mt = frag >> 6, kt = frag & 63;
    int gid = lane >> 2, tp = lane & 3;
    int r0 = mt * 16 + gid, c0 = kt * 16 + tp * 2;
    float2 x00 = *(const float2*)&X[(size_t)r0 * E + c0];
    float2 x10 = *(const float2*)&X[(size_t)(r0 + 8) * E + c0];
    float2 x01 = *(const float2*)&X[(size_t)r0 * E + c0 + 8];
    float2 x11 = *(const float2*)&X[(size_t)(r0 + 8) * E + c0 + 8];
    *(uint4*)&g_Xf[(size_t)idx * 4] =
        make_uint4(f22h(x00.x, x00.y), f22h(x10.x, x10.y),
                   f22h(x01.x, x01.y), f22h(x11.x, x11.y));
}

__global__ __launch_bounds__(256) void k_permWq(const float* __restrict__ W) {
    int idx  = blockIdx.x * 256 + threadIdx.x;
    int frag = idx >> 5, lane = idx & 31;
    int nt = frag >> 6, kt = frag & 63;
    int np = nt * 8 + (lane >> 2);                  // permuted col [which|h|d]
    int which = np >> 10, h = (np >> 6) & 15, d = np & 63;
    int c = d * 48 + which * 16 + h;                // original col
    int k0 = kt * 16 + (lane & 3) * 2;
    uint2 v;
    v.x = f22h(W[(size_t)k0 * NQKV + c],       W[(size_t)(k0 + 1) * NQKV + c]);
    v.y = f22h(W[(size_t)(k0 + 8) * NQKV + c], W[(size_t)(k0 + 9) * NQKV + c]);
    *(uint2*)&g_Wqf[(size_t)idx * 2] = v;
}

__global__ __launch_bounds__(256) void k_permWo(const float* __restrict__ W) {
    int idx  = blockIdx.x * 256 + threadIdx.x;
    int frag = idx >> 5, lane = idx & 31;
    int nt = frag >> 6, kt = frag & 63;
    int n = nt * 8 + (lane >> 2);
    int k0 = kt * 16 + (lane & 3) * 2;
    uint2 v;
    v.x = f22h(W[(size_t)k0 * E + n],       W[(size_t)(k0 + 1) * E + n]);
    v.y = f22h(W[(size_t)(k0 + 8) * E + n], W[(size_t)(k0 + 9) * E + n]);
    *(uint2*)&g_Wof[(size_t)idx * 2] = v;
}

// ---------------------------------------------------------------------------
// GEMM core: 128x128 tile, 8 warps (2m x 4n), warp 64x32 (round-7 config:
// 2 CTAs/SM). K-stage = 64 -> 16 stages; 3-stage cp.async.
// NEW: explicit fragment double-buffer across the 4 k16 sub-steps so the
// LDS->HMMA dependency is overlapped with mma issue.
// ---------------------------------------------------------------------------
constexpr int GEMM_SMEM_BYTES = 3 * 8192 * 4;   // 96KB

template <int EPI>   // 0 = QKV scatter, 1 = direct float out
__device__ __forceinline__ void gemm_core(const uint32_t* __restrict__ Af,
                                          const uint32_t* __restrict__ Bf,
                                          float* __restrict__ Cout) {
    extern __shared__ uint32_t smem[];     // [3][8192]
    const int tid = threadIdx.x, lane = tid & 31, warp = tid >> 5;
    const int wm = warp >> 2, wn = warp & 3;
    const int bm = blockIdx.y * 128, bn = blockIdx.x * 128;
    const int gid = lane >> 2, tig = lane & 3;

    auto issue = [&](int s) {
        uint32_t base = smem_u32(&smem[(s % 3) * 8192]);
        int ktb = s * 4;
#pragma unroll
        for (int it = 0; it < 4; it++) {   // A: 1024 chunks of 16B, frag=[ktl(4)][mtl(8)]
            int c = it * 256 + tid;
            int frag = c >> 5, off = c & 31;
            int mtl = frag & 7, ktl = frag >> 3;
            cpasync16(base + (frag * 128 + off * 4) * 4,
                      &Af[((size_t)((bm >> 4) + mtl) * 64 + ktb + ktl) * 128 + off * 4]);
        }
#pragma unroll
        for (int it = 0; it < 4; it++) {   // B: 1024 chunks, frag=[ktl(4)][ntl(16)]
            int c = it * 256 + tid;
            int frag = c >> 4, off = c & 15;
            int ntl = frag & 15, ktl = frag >> 4;
            cpasync16(base + 4096 * 4 + (frag * 64 + off * 4) * 4,
                      &Bf[((size_t)((bn >> 3) + ntl) * 64 + ktb + ktl) * 64 + off * 4]);
        }
        cp_commit();
    };

    float acc[4][4][4] = {};
    constexpr int NS = 16;
    issue(0);
    issue(1);
    for (int s = 0; s < NS; s++) {
        if (s < NS - 1) cp_wait<1>();
        else            cp_wait<0>();
        __syncthreads();
        if (s + 2 < NS) issue(s + 2);
        const uint32_t* As = &smem[(s % 3) * 8192];
        const uint32_t* Bs = As + 4096;

        // Fragment double-buffer across the 4 k16 sub-steps
        uint32_t af[2][4][4], bf[2][4][2];
        auto ldfrag = [&](int buf, int ks) {
#pragma unroll
            for (int i = 0; i < 4; i++)
                *(uint4*)af[buf][i] =
                    *(const uint4*)&As[((ks * 8 + wm * 4 + i) * 128) + lane * 4];
#pragma unroll
            for (int j = 0; j < 4; j++)
                *(uint2*)bf[buf][j] =
                    *(const uint2*)&Bs[((ks * 16 + wn * 4 + j) * 64) + lane * 2];
        };
        ldfrag(0, 0);
#pragma unroll
        for (int ks = 0; ks < 4; ks++) {
            if (ks < 3) ldfrag((ks + 1) & 1, ks + 1);
            const int cb = ks & 1;
#pragma unroll
            for (int i = 0; i < 4; i++)
#pragma unroll
                for (int j = 0; j < 4; j++)
                    mma16(acc[i][j], af[cb][i], bf[cb][j]);
        }
    }

    if (EPI == 0) {
        // QKV scatter into attention fragment layouts (cols permuted [which|h|d])
        const int which = bn >> 10;
#pragma unroll
        for (int i = 0; i < 4; i++) {
#pragma unroll
            for (int j = 0; j < 4; j++) {
                int m0  = bm + (wm * 4 + i) * 16 + gid;       // rows m0, m0+8
                int b_  = m0 >> 11, t0 = m0 & (T - 1);
                int np0 = bn + (wn * 4 + j) * 8 + tig * 2;
                int h = (np0 >> 6) & 15, d0 = np0 & 63;
                const float* a = acc[i][j];
                if (which == 0) {
                    size_t fb = (((size_t)(b_ * H + h) * (T / 16) + (t0 >> 4)) * 4 +
                                 (d0 >> 4)) * 32 + lane;
                    int rb = ((d0 >> 3) & 1) * 2;
                    g_Qf[fb * 4 + rb]     = f22h(a[0] * QSCALE, a[1] * QSCALE);
                    g_Qf[fb * 4 + rb + 1] = f22h(a[2] * QSCALE, a[3] * QSCALE);
                } else if (which == 1) {
                    int rg = (d0 >> 3) & 1;
                    size_t f0 = (((size_t)(b_ * H + h) * (T / 8) + (t0 >> 3)) * 4 +
                                 (d0 >> 4)) * 32 + lane;
                    size_t f1 = (((size_t)(b_ * H + h) * (T / 8) + ((t0 + 8) >> 3)) * 4 +
                                 (d0 >> 4)) * 32 + lane;
                    g_Kf[f0 * 2 + rg] = f22h(a[0], a[1]);
                    g_Kf[f1 * 2 + rg] = f22h(a[2], a[3]);
                } else {
                    __half* Vh = (__half*)g_Vf;
#pragma unroll
                    for (int r = 0; r < 4; r++) {
                        int tt = t0 + (r >> 1) * 8;
                        int d  = d0 + (r & 1);
                        int lv = ((d & 7) << 2) | ((tt & 7) >> 1);
                        int rv = (tt & 15) >> 3;
                        size_t w = ((((size_t)(b_ * H + h) * (T / 16) + (tt >> 4)) * 8 +
                                     (d >> 3)) * 32 + lv) * 2 + rv;
                        Vh[w * 2 + (tt & 1)] = __float2half_rn(a[r]);
                    }
                }
            }
        }
    } else {
#pragma unroll
        for (int i = 0; i < 4; i++) {
#pragma unroll
            for (int j = 0; j < 4; j++) {
#pragma unroll
                for (int rh = 0; rh < 2; rh++) {
                    int m = bm + (wm * 4 + i) * 16 + gid + rh * 8;
                    int n = bn + (wn * 4 + j) * 8 + tig * 2;
                    *(float2*)&Cout[(size_t)m * E + n] =
                        make_float2(acc[i][j][rh * 2], acc[i][j][rh * 2 + 1]);
                }
            }
        }
    }
}

__global__ __launch_bounds__(256) void k_qkv() {
    gemm_core<0>(g_Xf, g_Wqf, nullptr);
}
__global__ __launch_bounds__(256) void k_out(float* __restrict__ Cout) {
    gemm_core<1>(g_AOf, g_Wof, Cout);
}

// ---------------------------------------------------------------------------
// Flash attention (round-7, unchanged): no online max, BLOCK_M=128
// (8 warps x 16 rows), BLOCK_N=64, D=64, fp16 mma, exp via ex2.approx.
// ---------------------------------------------------------------------------
constexpr int ATTN_SMEM_BYTES = 2 * 4096 * 4;   // 32KB

__global__ __launch_bounds__(256) void k_attn() {
    extern __shared__ uint32_t sm[];
    const int tid = threadIdx.x, lane = tid & 31, warp = tid >> 5;
    const int bh = blockIdx.y;
    const int bm = blockIdx.x * 128;

    const uint32_t* __restrict__ Kfb = g_Kf + (size_t)bh * (T / 8) * 4 * 64;
    const uint32_t* __restrict__ Vfb = g_Vf + (size_t)bh * (T / 16) * 8 * 64;

    uint32_t qf[4][4];
    {
        const uint32_t* qsrc =
            g_Qf + ((size_t)bh * (T / 16) + (bm >> 4) + warp) * 4 * 128;
#pragma unroll
        for (int dt = 0; dt < 4; dt++)
            *(uint4*)qf[dt] = *(const uint4*)&qsrc[dt * 128 + lane * 4];
    }

    auto issue = [&](int s) {
        uint32_t sK = smem_u32(&sm[(s & 1) * 4096]);
        uint32_t sV = sK + 2048 * 4;
        int jb8 = s * 8, jb16 = s * 4;
#pragma unroll
        for (int it = 0; it < 2; it++) {
            int c = it * 256 + tid;
            int f = c >> 4, off = c & 15;
            cpasync16(sK + (f * 64 + off * 4) * 4,
                      &Kfb[((size_t)(jb8 + (f >> 2)) * 4 + (f & 3)) * 64 + off * 4]);
        }
#pragma unroll
        for (int it = 0; it < 2; it++) {
            int c = it * 256 + tid;
            int f = c >> 4, off = c & 15;
            cpasync16(sV + (f * 64 + off * 4) * 4,
                      &Vfb[((size_t)(jb16 + (f >> 3)) * 8 + (f & 7)) * 64 + off * 4]);
        }
        cp_commit();
    };

    float li[2] = {0.f, 0.f};
    float o[8][4] = {};

    constexpr int NS = T / 64;   // 32
    issue(0);
    for (int it = 0; it < NS; it++) {
        if (it + 1 < NS) { issue(it + 1); cp_wait<1>(); }
        else             { cp_wait<0>(); }
        __syncthreads();
        const uint32_t* Ks = &sm[(it & 1) * 4096];
        const uint32_t* Vs = Ks + 2048;

        // S = Q K^T (log2-domain scores)
        float s[8][4] = {};
#pragma unroll
        for (int dt = 0; dt < 4; dt++) {
#pragma unroll
            for (int jt = 0; jt < 8; jt++) {
                uint32_t bf[2];
                *(uint2*)bf = *(const uint2*)&Ks[((jt * 4 + dt) * 64) + lane * 2];
                mma16(s[jt], qf[dt], bf);
            }
        }

        // P = exp2(S), accumulate row sums
#pragma unroll
        for (int jt = 0; jt < 8; jt++) {
#pragma unroll
            for (int r = 0; r < 4; r++)
                s[jt][r] = ex2(s[jt][r]);
            li[0] += s[jt][0] + s[jt][1];
            li[1] += s[jt][2] + s[jt][3];
        }

        // O += P V (P C-frag -> A-frag in registers; lane map is identity)
#pragma unroll
        for (int kt = 0; kt < 4; kt++) {
            uint32_t pf[4];
            pf[0] = f22h(s[2 * kt][0],     s[2 * kt][1]);
            pf[1] = f22h(s[2 * kt][2],     s[2 * kt][3]);
            pf[2] = f22h(s[2 * kt + 1][0], s[2 * kt + 1][1]);
            pf[3] = f22h(s[2 * kt + 1][2], s[2 * kt + 1][3]);
#pragma unroll
            for (int dn = 0; dn < 8; dn++) {
                uint32_t bf[2];
                *(uint2*)bf = *(const uint2*)&Vs[((kt * 8 + dn) * 64) + lane * 2];
                mma16(o[dn], pf, bf);
            }
        }
        __syncthreads();
    }

    // Quad-reduce row sums once
#pragma unroll
    for (int h = 0; h < 2; h++) {
        li[h] += __shfl_xor_sync(0xffffffffu, li[h], 1);
        li[h] += __shfl_xor_sync(0xffffffffu, li[h], 2);
    }
    float inv[2] = {1.f / li[0], 1.f / li[1]};

    // Epilogue: AO -> A-frags for k_out (m = b*T+t, k = h*64+d)
    const int b_ = bh >> 4, h_ = bh & 15;
    const int mt = ((b_ * T + bm) >> 4) + warp;
#pragma unroll
    for (int dn = 0; dn < 8; dn++) {
        int kt = h_ * 4 + (dn >> 1);
        int rb = (dn & 1) * 2;
        size_t fb = ((size_t)mt * 64 + kt) * 32 + lane;
        g_AOf[fb * 4 + rb]     = f22h(o[dn][0] * inv[0], o[dn][1] * inv[0]);
        g_AOf[fb * 4 + rb + 1] = f22h(o[dn][2] * inv[1], o[dn][3] * inv[1]);
    }
}

// ---------------------------------------------------------------------------
extern "C" void kernel_launch(void* const* d_in, const int* in_sizes, int n_in,
                              void* d_out, int out_size) {
    const float* x     = (const float*)d_in[0];
    const float* w_qkv = (const float*)d_in[1];
    const float* w_out = (const float*)d_in[2];
    float* out = (float*)d_out;

    cudaFuncSetAttribute(k_attn, cudaFuncAttributeMaxDynamicSharedMemorySize,
                         ATTN_SMEM_BYTES);
    cudaFuncSetAttribute(k_qkv, cudaFuncAttributeMaxDynamicSharedMemorySize,
                         GEMM_SMEM_BYTES);
    cudaFuncSetAttribute(k_out, cudaFuncAttributeMaxDynamicSharedMemorySize,
                         GEMM_SMEM_BYTES);

    // Pre-passes: fragment-ordered fp16 operands
    k_permA <<<(M / 16) * (E / 16) * 32 / 256, 256>>>(x);
    k_permWq<<<(NQKV / 8) * (E / 16) * 32 / 256, 256>>>(w_qkv);
    k_permWo<<<(E / 8) * (HD / 16) * 32 / 256, 256>>>(w_out);

    k_qkv<<<dim3(NQKV / 128, M / 128), 256, GEMM_SMEM_BYTES>>>();
    k_attn<<<dim3(T / 128, B * H), 256, ATTN_SMEM_BYTES>>>();
    k_out<<<dim3(E / 128, M / 128), 256, GEMM_SMEM_BYTES>>>(out);
}

// round 11
// speedup vs baseline: 1.0497x; 1.0250x over previous
#include <cuda_runtime.h>
#include <cuda_fp16.h>
#include <math_constants.h>
#include <cstdint>

// Problem constants
constexpr int B  = 2;
constexpr int T  = 2048;
constexpr int E  = 1024;
constexpr int H  = 16;
constexpr int DH = 64;
constexpr int M    = B * T;        // 4096
constexpr int NQKV = 3 * H * DH;   // 3072
constexpr int HD   = H * DH;       // 1024

// Q pre-scale: DH^-0.5 * log2(e)  (attention uses exp2)
#define QSCALE 0.180336880972f

// ---------------------------------------------------------------------------
// fp16 m16n8k16 fragment layouts (PTX ISA):
// A (16x16) elem (r,c): lane=((r&7)<<2)|((c&7)>>1), reg=((c>>3)<<1)|((r>>3)&1), half=c&1
// B (16x8)  elem (k,n): lane=((n&7)<<2)|((k&7)>>1), reg=(k>>3)&1,               half=k&1
// C f32 (16x8): c0=(gid,2t) c1=(gid,2t+1) c2=(gid+8,2t) c3=(gid+8,2t+1)
// C f16 (16x8): reg0 = half2{(gid,2t),(gid,2t+1)}, reg1 = half2{(gid+8,...)}
// ---------------------------------------------------------------------------
__device__ uint32_t g_Xf  [(size_t)(M / 16) * (E / 16) * 128];
__device__ uint32_t g_Wqf [(size_t)(NQKV / 8) * (E / 16) * 64];
__device__ uint32_t g_Wof [(size_t)(E / 8) * (HD / 16) * 64];
__device__ uint32_t g_Qf  [(size_t)(B * H) * (T / 16) * 4 * 128];
__device__ uint32_t g_Kf  [(size_t)(B * H) * (T / 8) * 4 * 64];
__device__ uint32_t g_Vf  [(size_t)(B * H) * (T / 16) * 8 * 64];
__device__ uint32_t g_AOf [(size_t)(M / 16) * (HD / 16) * 128];

// ---------------------------------------------------------------------------
// Helpers
// ---------------------------------------------------------------------------
__device__ __forceinline__ uint32_t f22h(float a, float b) {
    __half2 h = __floats2half2_rn(a, b);
    return *(uint32_t*)&h;
}
__device__ __forceinline__ float ex2(float x) {
    float y;
    asm("ex2.approx.f32 %0, %1;" : "=f"(y) : "f"(x));
    return y;
}
__device__ __forceinline__ uint32_t smem_u32(const void* p) {
    return (uint32_t)__cvta_generic_to_shared(p);
}
__device__ __forceinline__ void cpasync16(uint32_t dst, const void* src) {
    asm volatile("cp.async.cg.shared.global [%0], [%1], 16;" :: "r"(dst), "l"(src));
}
__device__ __forceinline__ void cp_commit() { asm volatile("cp.async.commit_group;"); }
template <int N>
__device__ __forceinline__ void cp_wait() { asm volatile("cp.async.wait_group %0;" :: "n"(N)); }

// f32-accumulator fp16 mma
__device__ __forceinline__ void mma16(float* c, const uint32_t* a, const uint32_t* b) {
    asm volatile(
        "mma.sync.aligned.m16n8k16.row.col.f32.f16.f16.f32 "
        "{%0,%1,%2,%3}, {%4,%5,%6,%7}, {%8,%9}, {%0,%1,%2,%3};"
        : "+f"(c[0]), "+f"(c[1]), "+f"(c[2]), "+f"(c[3])
        : "r"(a[0]), "r"(a[1]), "r"(a[2]), "r"(a[3]), "r"(b[0]), "r"(b[1]));
}
// f16-accumulator fp16 mma (S = QK^T only; K=64 keeps accumulation error tiny)
__device__ __forceinline__ void mma16h(uint32_t* c, const uint32_t* a, const uint32_t* b) {
    asm volatile(
        "mma.sync.aligned.m16n8k16.row.col.f16.f16.f16.f16 "
        "{%0,%1}, {%2,%3,%4,%5}, {%6,%7}, {%0,%1};"
        : "+r"(c[0]), "+r"(c[1])
        : "r"(a[0]), "r"(a[1]), "r"(a[2]), "r"(a[3]), "r"(b[0]), "r"(b[1]));
}

// ---------------------------------------------------------------------------
// Fused pre-pass: fragment-ordered fp16 operands for all three tensors.
// Block ranges: [0,2048) permA | [2048,5120) permWq | [5120,6144) permWo
// ---------------------------------------------------------------------------
constexpr int PERM_A_BLOCKS  = (M / 16) * (E / 16) * 32 / 256;     // 2048
constexpr int PERM_WQ_BLOCKS = (NQKV / 8) * (E / 16) * 32 / 256;   // 3072
constexpr int PERM_WO_BLOCKS = (E / 8) * (HD / 16) * 32 / 256;     // 1024
constexpr int PERM_BLOCKS    = PERM_A_BLOCKS + PERM_WQ_BLOCKS + PERM_WO_BLOCKS;

__global__ __launch_bounds__(256) void k_perm(const float* __restrict__ X,
                                              const float* __restrict__ Wq,
                                              const float* __restrict__ Wo) {
    int blk = blockIdx.x;
    if (blk < PERM_A_BLOCKS) {
        int idx  = blk * 256 + threadIdx.x;
        int frag = idx >> 5, lane = idx & 31;
        int mt = frag >> 6, kt = frag & 63;
        int gid = lane >> 2, tp = lane & 3;
        int r0 = mt * 16 + gid, c0 = kt * 16 + tp * 2;
        float2 x00 = *(const float2*)&X[(size_t)r0 * E + c0];
        float2 x10 = *(const float2*)&X[(size_t)(r0 + 8) * E + c0];
        float2 x01 = *(const float2*)&X[(size_t)r0 * E + c0 + 8];
        float2 x11 = *(const float2*)&X[(size_t)(r0 + 8) * E + c0 + 8];
        *(uint4*)&g_Xf[(size_t)idx * 4] =
            make_uint4(f22h(x00.x, x00.y), f22h(x10.x, x10.y),
                       f22h(x01.x, x01.y), f22h(x11.x, x11.y));
    } else if (blk < PERM_A_BLOCKS + PERM_WQ_BLOCKS) {
        int idx  = (blk - PERM_A_BLOCKS) * 256 + threadIdx.x;
        int frag = idx >> 5, lane = idx & 31;
        int nt = frag >> 6, kt = frag & 63;
        int np = nt * 8 + (lane >> 2);              // permuted col [which|h|d]
        int which = np >> 10, h = (np >> 6) & 15, d = np & 63;
        int c = d * 48 + which * 16 + h;            // original col
        int k0 = kt * 16 + (lane & 3) * 2;
        uint2 v;
        v.x = f22h(Wq[(size_t)k0 * NQKV + c],       Wq[(size_t)(k0 + 1) * NQKV + c]);
        v.y = f22h(Wq[(size_t)(k0 + 8) * NQKV + c], Wq[(size_t)(k0 + 9) * NQKV + c]);
        *(uint2*)&g_Wqf[(size_t)idx * 2] = v;
    } else {
        int idx  = (blk - PERM_A_BLOCKS - PERM_WQ_BLOCKS) * 256 + threadIdx.x;
        int frag = idx >> 5, lane = idx & 31;
        int nt = frag >> 6, kt = frag & 63;
        int n = nt * 8 + (lane >> 2);
        int k0 = kt * 16 + (lane & 3) * 2;
        uint2 v;
        v.x = f22h(Wo[(size_t)k0 * E + n],       Wo[(size_t)(k0 + 1) * E + n]);
        v.y = f22h(Wo[(size_t)(k0 + 8) * E + n], Wo[(size_t)(k0 + 9) * E + n]);
        *(uint2*)&g_Wof[(size_t)idx * 2] = v;
    }
}

// ---------------------------------------------------------------------------
// GEMM core (round-7 config, best measured): 128x128 tile, 8 warps (2m x 4n),
// warp 64x32, K-stage = 64 -> 16 stages, 3-stage cp.async, plain inner loop.
// ---------------------------------------------------------------------------
constexpr int GEMM_SMEM_BYTES = 3 * 8192 * 4;   // 96KB

template <int EPI>   // 0 = QKV scatter, 1 = direct float out
__device__ __forceinline__ void gemm_core(const uint32_t* __restrict__ Af,
                                          const uint32_t* __restrict__ Bf,
                                          float* __restrict__ Cout) {
    extern __shared__ uint32_t smem[];     // [3][8192]
    const int tid = threadIdx.x, lane = tid & 31, warp = tid >> 5;
    const int wm = warp >> 2, wn = warp & 3;
    const int bm = blockIdx.y * 128, bn = blockIdx.x * 128;
    const int gid = lane >> 2, tig = lane & 3;

    auto issue = [&](int s) {
        uint32_t base = smem_u32(&smem[(s % 3) * 8192]);
        int ktb = s * 4;
#pragma unroll
        for (int it = 0; it < 4; it++) {   // A: 1024 chunks of 16B, frag=[ktl(4)][mtl(8)]
            int c = it * 256 + tid;
            int frag = c >> 5, off = c & 31;
            int mtl = frag & 7, ktl = frag >> 3;
            cpasync16(base + (frag * 128 + off * 4) * 4,
                      &Af[((size_t)((bm >> 4) + mtl) * 64 + ktb + ktl) * 128 + off * 4]);
        }
#pragma unroll
        for (int it = 0; it < 4; it++) {   // B: 1024 chunks, frag=[ktl(4)][ntl(16)]
            int c = it * 256 + tid;
            int frag = c >> 4, off = c & 15;
            int ntl = frag & 15, ktl = frag >> 4;
            cpasync16(base + 4096 * 4 + (frag * 64 + off * 4) * 4,
                      &Bf[((size_t)((bn >> 3) + ntl) * 64 + ktb + ktl) * 64 + off * 4]);
        }
        cp_commit();
    };

    float acc[4][4][4] = {};
    constexpr int NS = 16;
    issue(0);
    issue(1);
    for (int s = 0; s < NS; s++) {
        if (s < NS - 1) cp_wait<1>();
        else            cp_wait<0>();
        __syncthreads();
        if (s + 2 < NS) issue(s + 2);
        const uint32_t* As = &smem[(s % 3) * 8192];
        const uint32_t* Bs = As + 4096;
#pragma unroll
        for (int ks = 0; ks < 4; ks++) {
            uint32_t af[4][4], bf[4][2];
#pragma unroll
            for (int i = 0; i < 4; i++)
                *(uint4*)af[i] = *(const uint4*)&As[((ks * 8 + wm * 4 + i) * 128) + lane * 4];
#pragma unroll
            for (int j = 0; j < 4; j++)
                *(uint2*)bf[j] = *(const uint2*)&Bs[((ks * 16 + wn * 4 + j) * 64) + lane * 2];
#pragma unroll
            for (int i = 0; i < 4; i++)
#pragma unroll
                for (int j = 0; j < 4; j++)
                    mma16(acc[i][j], af[i], bf[j]);
        }
    }

    if (EPI == 0) {
        // QKV scatter into attention fragment layouts (cols permuted [which|h|d])
        const int which = bn >> 10;
#pragma unroll
        for (int i = 0; i < 4; i++) {
#pragma unroll
            for (int j = 0; j < 4; j++) {
                int m0  = bm + (wm * 4 + i) * 16 + gid;       // rows m0, m0+8
                int b_  = m0 >> 11, t0 = m0 & (T - 1);
                int np0 = bn + (wn * 4 + j) * 8 + tig * 2;
                int h = (np0 >> 6) & 15, d0 = np0 & 63;
                const float* a = acc[i][j];
                if (which == 0) {
                    size_t fb = (((size_t)(b_ * H + h) * (T / 16) + (t0 >> 4)) * 4 +
                                 (d0 >> 4)) * 32 + lane;
                    int rb = ((d0 >> 3) & 1) * 2;
                    g_Qf[fb * 4 + rb]     = f22h(a[0] * QSCALE, a[1] * QSCALE);
                    g_Qf[fb * 4 + rb + 1] = f22h(a[2] * QSCALE, a[3] * QSCALE);
                } else if (which == 1) {
                    int rg = (d0 >> 3) & 1;
                    size_t f0 = (((size_t)(b_ * H + h) * (T / 8) + (t0 >> 3)) * 4 +
                                 (d0 >> 4)) * 32 + lane;
                    size_t f1 = (((size_t)(b_ * H + h) * (T / 8) + ((t0 + 8) >> 3)) * 4 +
                                 (d0 >> 4)) * 32 + lane;
                    g_Kf[f0 * 2 + rg] = f22h(a[0], a[1]);
                    g_Kf[f1 * 2 + rg] = f22h(a[2], a[3]);
                } else {
                    __half* Vh = (__half*)g_Vf;
#pragma unroll
                    for (int r = 0; r < 4; r++) {
                        int tt = t0 + (r >> 1) * 8;
                        int d  = d0 + (r & 1);
                        int lv = ((d & 7) << 2) | ((tt & 7) >> 1);
                        int rv = (tt & 15) >> 3;
                        size_t w = ((((size_t)(b_ * H + h) * (T / 16) + (tt >> 4)) * 8 +
                                     (d >> 3)) * 32 + lv) * 2 + rv;
                        Vh[w * 2 + (tt & 1)] = __float2half_rn(a[r]);
                    }
                }
            }
        }
    } else {
#pragma unroll
        for (int i = 0; i < 4; i++) {
#pragma unroll
            for (int j = 0; j < 4; j++) {
#pragma unroll
                for (int rh = 0; rh < 2; rh++) {
                    int m = bm + (wm * 4 + i) * 16 + gid + rh * 8;
                    int n = bn + (wn * 4 + j) * 8 + tig * 2;
                    *(float2*)&Cout[(size_t)m * E + n] =
                        make_float2(acc[i][j][rh * 2], acc[i][j][rh * 2 + 1]);
                }
            }
        }
    }
}

__global__ __launch_bounds__(256) void k_qkv() {
    gemm_core<0>(g_Xf, g_Wqf, nullptr);
}
__global__ __launch_bounds__(256) void k_out(float* __restrict__ Cout) {
    gemm_core<1>(g_AOf, g_Wof, Cout);
}

// ---------------------------------------------------------------------------
// Flash attention, no online max. BLOCK_M=128 (8 warps x 16 rows), BLOCK_N=64.
// NEW: S = Q K^T uses f16 accumulators (K=64, error ~2e-4); its packed C-frag
// layout equals the PV A-frag layout. PV keeps f32 accumulators.
// ---------------------------------------------------------------------------
constexpr int ATTN_SMEM_BYTES = 2 * 4096 * 4;   // 32KB

__global__ __launch_bounds__(256) void k_attn() {
    extern __shared__ uint32_t sm[];
    const int tid = threadIdx.x, lane = tid & 31, warp = tid >> 5;
    const int bh = blockIdx.y;
    const int bm = blockIdx.x * 128;

    const uint32_t* __restrict__ Kfb = g_Kf + (size_t)bh * (T / 8) * 4 * 64;
    const uint32_t* __restrict__ Vfb = g_Vf + (size_t)bh * (T / 16) * 8 * 64;

    uint32_t qf[4][4];
    {
        const uint32_t* qsrc =
            g_Qf + ((size_t)bh * (T / 16) + (bm >> 4) + warp) * 4 * 128;
#pragma unroll
        for (int dt = 0; dt < 4; dt++)
            *(uint4*)qf[dt] = *(const uint4*)&qsrc[dt * 128 + lane * 4];
    }

    auto issue = [&](int s) {
        uint32_t sK = smem_u32(&sm[(s & 1) * 4096]);
        uint32_t sV = sK + 2048 * 4;
        int jb8 = s * 8, jb16 = s * 4;
#pragma unroll
        for (int it = 0; it < 2; it++) {
            int c = it * 256 + tid;
            int f = c >> 4, off = c & 15;
            cpasync16(sK + (f * 64 + off * 4) * 4,
                      &Kfb[((size_t)(jb8 + (f >> 2)) * 4 + (f & 3)) * 64 + off * 4]);
        }
#pragma unroll
        for (int it = 0; it < 2; it++) {
            int c = it * 256 + tid;
            int f = c >> 4, off = c & 15;
            cpasync16(sV + (f * 64 + off * 4) * 4,
                      &Vfb[((size_t)(jb16 + (f >> 3)) * 8 + (f & 7)) * 64 + off * 4]);
        }
        cp_commit();
    };

    float li[2] = {0.f, 0.f};
    float o[8][4] = {};

    constexpr int NS = T / 64;   // 32
    issue(0);
    for (int it = 0; it < NS; it++) {
        if (it + 1 < NS) { issue(it + 1); cp_wait<1>(); }
        else             { cp_wait<0>(); }
        __syncthreads();
        const uint32_t* Ks = &sm[(it & 1) * 4096];
        const uint32_t* Vs = Ks + 2048;

        // S = Q K^T (f16 accumulators, packed half2 C-frags)
        uint32_t sh[8][2] = {};   // packed f16 zero == 0x0
#pragma unroll
        for (int dt = 0; dt < 4; dt++) {
#pragma unroll
            for (int jt = 0; jt < 8; jt++) {
                uint32_t bf[2];
                *(uint2*)bf = *(const uint2*)&Ks[((jt * 4 + dt) * 64) + lane * 2];
                mma16h(sh[jt], qf[dt], bf);
            }
        }

        // P = exp2(S): unpack, ex2, accumulate row sums, repack as PV A-frags
        float p[8][4];
#pragma unroll
        for (int jt = 0; jt < 8; jt++) {
            float2 f0 = __half22float2(*(__half2*)&sh[jt][0]);  // row gid
            float2 f1 = __half22float2(*(__half2*)&sh[jt][1]);  // row gid+8
            p[jt][0] = ex2(f0.x); p[jt][1] = ex2(f0.y);
            p[jt][2] = ex2(f1.x); p[jt][3] = ex2(f1.y);
            li[0] += p[jt][0] + p[jt][1];
            li[1] += p[jt][2] + p[jt][3];
        }

        // O += P V (f32 accumulators)
#pragma unroll
        for (int kt = 0; kt < 4; kt++) {
            uint32_t pf[4];
            pf[0] = f22h(p[2 * kt][0],     p[2 * kt][1]);
            pf[1] = f22h(p[2 * kt][2],     p[2 * kt][3]);
            pf[2] = f22h(p[2 * kt + 1][0], p[2 * kt + 1][1]);
            pf[3] = f22h(p[2 * kt + 1][2], p[2 * kt + 1][3]);
#pragma unroll
            for (int dn = 0; dn < 8; dn++) {
                uint32_t bf[2];
                *(uint2*)bf = *(const uint2*)&Vs[((kt * 8 + dn) * 64) + lane * 2];
                mma16(o[dn], pf, bf);
            }
        }
        __syncthreads();
    }

    // Quad-reduce row sums once
#pragma unroll
    for (int h = 0; h < 2; h++) {
        li[h] += __shfl_xor_sync(0xffffffffu, li[h], 1);
        li[h] += __shfl_xor_sync(0xffffffffu, li[h], 2);
    }
    float inv[2] = {1.f / li[0], 1.f / li[1]};

    // Epilogue: AO -> A-frags for k_out (m = b*T+t, k = h*64+d)
    const int b_ = bh >> 4, h_ = bh & 15;
    const int mt = ((b_ * T + bm) >> 4) + warp;
#pragma unroll
    for (int dn = 0; dn < 8; dn++) {
        int kt = h_ * 4 + (dn >> 1);
        int rb = (dn & 1) * 2;
        size_t fb = ((size_t)mt * 64 + kt) * 32 + lane;
        g_AOf[fb * 4 + rb]     = f22h(o[dn][0] * inv[0], o[dn][1] * inv[0]);
        g_AOf[fb * 4 + rb + 1] = f22h(o[dn][2] * inv[1], o[dn][3] * inv[1]);
    }
}

// ---------------------------------------------------------------------------
extern "C" void kernel_launch(void* const* d_in, const int* in_sizes, int n_in,
                              void* d_out, int out_size) {
    const float* x     = (const float*)d_in[0];
    const float* w_qkv = (const float*)d_in[1];
    const float* w_out = (const float*)d_in[2];
    float* out = (float*)d_out;

    cudaFuncSetAttribute(k_attn, cudaFuncAttributeMaxDynamicSharedMemorySize,
                         ATTN_SMEM_BYTES);
    cudaFuncSetAttribute(k_qkv, cudaFuncAttributeMaxDynamicSharedMemorySize,
                         GEMM_SMEM_BYTES);
    cudaFuncSetAttribute(k_out, cudaFuncAttributeMaxDynamicSharedMemorySize,
                         GEMM_SMEM_BYTES);

    k_perm<<<PERM_BLOCKS, 256>>>(x, w_qkv, w_out);
    k_qkv<<<dim3(NQKV / 128, M / 128), 256, GEMM_SMEM_BYTES>>>();
    k_attn<<<dim3(T / 128, B * H), 256, ATTN_SMEM_BYTES>>>();
    k_out<<<dim3(E / 128, M / 128), 256, GEMM_SMEM_BYTES>>>(out);
}

// round 14
// speedup vs baseline: 1.0508x; 1.0010x over previous
#include <cuda_runtime.h>
#include <cuda_fp16.h>
#include <math_constants.h>
#include <cstdint>

// Problem constants
constexpr int B  = 2;
constexpr int T  = 2048;
constexpr int E  = 1024;
constexpr int H  = 16;
constexpr int DH = 64;
constexpr int M    = B * T;        // 4096
constexpr int NQKV = 3 * H * DH;   // 3072
constexpr int HD   = H * DH;       // 1024

// Q pre-scale: DH^-0.5 * log2(e)  (attention uses exp2)
#define QSCALE 0.180336880972f

// ---------------------------------------------------------------------------
// fp16 m16n8k16 fragment layouts (PTX ISA):
// A (16x16) elem (r,c): lane=((r&7)<<2)|((c&7)>>1), reg=((c>>3)<<1)|((r>>3)&1), half=c&1
// B (16x8)  elem (k,n): lane=((n&7)<<2)|((k&7)>>1), reg=(k>>3)&1,               half=k&1
// C f32 (16x8): c0=(gid,2t) c1=(gid,2t+1) c2=(gid+8,2t) c3=(gid+8,2t+1)
// ---------------------------------------------------------------------------
__device__ uint32_t g_Xf  [(size_t)(M / 16) * (E / 16) * 128];
__device__ uint32_t g_Wqf [(size_t)(NQKV / 8) * (E / 16) * 64];
__device__ uint32_t g_Wof [(size_t)(E / 8) * (HD / 16) * 64];
__device__ uint32_t g_Qf  [(size_t)(B * H) * (T / 16) * 4 * 128];
__device__ uint32_t g_Kf  [(size_t)(B * H) * (T / 8) * 4 * 64];
__device__ uint32_t g_Vf  [(size_t)(B * H) * (T / 16) * 8 * 64];
__device__ uint32_t g_AOf [(size_t)(M / 16) * (HD / 16) * 128];

// ---------------------------------------------------------------------------
// Helpers
// ---------------------------------------------------------------------------
__device__ __forceinline__ uint32_t f22h(float a, float b) {
    __half2 h = __floats2half2_rn(a, b);
    return *(uint32_t*)&h;
}
__device__ __forceinline__ uint32_t smem_u32(const void* p) {
    return (uint32_t)__cvta_generic_to_shared(p);
}
__device__ __forceinline__ void cpasync16(uint32_t dst, const void* src) {
    asm volatile("cp.async.cg.shared.global [%0], [%1], 16;" :: "r"(dst), "l"(src));
}
__device__ __forceinline__ void cp_commit() { asm volatile("cp.async.commit_group;"); }
template <int N>
__device__ __forceinline__ void cp_wait() { asm volatile("cp.async.wait_group %0;" :: "n"(N)); }

__device__ __forceinline__ void mma16(float* c, const uint32_t* a, const uint32_t* b) {
    asm volatile(
        "mma.sync.aligned.m16n8k16.row.col.f32.f16.f16.f32 "
        "{%0,%1,%2,%3}, {%4,%5,%6,%7}, {%8,%9}, {%0,%1,%2,%3};"
        : "+f"(c[0]), "+f"(c[1]), "+f"(c[2]), "+f"(c[3])
        : "r"(a[0]), "r"(a[1]), "r"(a[2]), "r"(a[3]), "r"(b[0]), "r"(b[1]));
}

// ---------------------------------------------------------------------------
// Fused pre-pass (round-11, measured passing): fragment-ordered fp16 operands.
// Block ranges: [0,2048) permA | [2048,5120) permWq | [5120,6144) permWo
// ---------------------------------------------------------------------------
constexpr int PERM_A_BLOCKS  = (M / 16) * (E / 16) * 32 / 256;     // 2048
constexpr int PERM_WQ_BLOCKS = (NQKV / 8) * (E / 16) * 32 / 256;   // 3072
constexpr int PERM_WO_BLOCKS = (E / 8) * (HD / 16) * 32 / 256;     // 1024
constexpr int PERM_BLOCKS    = PERM_A_BLOCKS + PERM_WQ_BLOCKS + PERM_WO_BLOCKS;

__global__ __launch_bounds__(256) void k_perm(const float* __restrict__ X,
                                              const float* __restrict__ Wq,
                                              const float* __restrict__ Wo) {
    int blk = blockIdx.x;
    if (blk < PERM_A_BLOCKS) {
        int idx  = blk * 256 + threadIdx.x;
        int frag = idx >> 5, lane = idx & 31;
        int mt = frag >> 6, kt = frag & 63;
        int gid = lane >> 2, tp = lane & 3;
        int r0 = mt * 16 + gid, c0 = kt * 16 + tp * 2;
        float2 x00 = *(const float2*)&X[(size_t)r0 * E + c0];
        float2 x10 = *(const float2*)&X[(size_t)(r0 + 8) * E + c0];
        float2 x01 = *(const float2*)&X[(size_t)r0 * E + c0 + 8];
        float2 x11 = *(const float2*)&X[(size_t)(r0 + 8) * E + c0 + 8];
        *(uint4*)&g_Xf[(size_t)idx * 4] =
            make_uint4(f22h(x00.x, x00.y), f22h(x10.x, x10.y),
                       f22h(x01.x, x01.y), f22h(x11.x, x11.y));
    } else if (blk < PERM_A_BLOCKS + PERM_WQ_BLOCKS) {
        int idx  = (blk - PERM_A_BLOCKS) * 256 + threadIdx.x;
        int frag = idx >> 5, lane = idx & 31;
        int nt = frag >> 6, kt = frag & 63;
        int np = nt * 8 + (lane >> 2);              // permuted col [which|h|d]
        int which = np >> 10, h = (np >> 6) & 15, d = np & 63;
        int c = d * 48 + which * 16 + h;            // original col
        int k0 = kt * 16 + (lane & 3) * 2;
        uint2 v;
        v.x = f22h(Wq[(size_t)k0 * NQKV + c],       Wq[(size_t)(k0 + 1) * NQKV + c]);
        v.y = f22h(Wq[(size_t)(k0 + 8) * NQKV + c], Wq[(size_t)(k0 + 9) * NQKV + c]);
        *(uint2*)&g_Wqf[(size_t)idx * 2] = v;
    } else {
        int idx  = (blk - PERM_A_BLOCKS - PERM_WQ_BLOCKS) * 256 + threadIdx.x;
        int frag = idx >> 5, lane = idx & 31;
        int nt = frag >> 6, kt = frag & 63;
        int n = nt * 8 + (lane >> 2);
        int k0 = kt * 16 + (lane & 3) * 2;
        uint2 v;
        v.x = f22h(Wo[(size_t)k0 * E + n],       Wo[(size_t)(k0 + 1) * E + n]);
        v.y = f22h(Wo[(size_t)(k0 + 8) * E + n], Wo[(size_t)(k0 + 9) * E + n]);
        *(uint2*)&g_Wof[(size_t)idx * 2] = v;
    }
}

// ---------------------------------------------------------------------------
// GEMM core (round-7 config, best measured): 128x128 tile, 8 warps (2m x 4n),
// warp 64x32, K-stage = 64 -> 16 stages, 3-stage cp.async, plain inner loop.
// ---------------------------------------------------------------------------
constexpr int GEMM_SMEM_BYTES = 3 * 8192 * 4;   // 96KB

template <int EPI>   // 0 = QKV scatter, 1 = direct float out
__device__ __forceinline__ void gemm_core(const uint32_t* __restrict__ Af,
                                          const uint32_t* __restrict__ Bf,
                                          float* __restrict__ Cout) {
    extern __shared__ uint32_t smem[];     // [3][8192]
    const int tid = threadIdx.x, lane = tid & 31, warp = tid >> 5;
    const int wm = warp >> 2, wn = warp & 3;
    const int bm = blockIdx.y * 128, bn = blockIdx.x * 128;
    const int gid = lane >> 2, tig = lane & 3;

    auto issue = [&](int s) {
        uint32_t base = smem_u32(&smem[(s % 3) * 8192]);
        int ktb = s * 4;
#pragma unroll
        for (int it = 0; it < 4; it++) {   // A: 1024 chunks of 16B, frag=[ktl(4)][mtl(8)]
            int c = it * 256 + tid;
            int frag = c >> 5, off = c & 31;
            int mtl = frag & 7, ktl = frag >> 3;
            cpasync16(base + (frag * 128 + off * 4) * 4,
                      &Af[((size_t)((bm >> 4) + mtl) * 64 + ktb + ktl) * 128 + off * 4]);
        }
#pragma unroll
        for (int it = 0; it < 4; it++) {   // B: 1024 chunks, frag=[ktl(4)][ntl(16)]
            int c = it * 256 + tid;
            int frag = c >> 4, off = c & 15;
            int ntl = frag & 15, ktl = frag >> 4;
            cpasync16(base + 4096 * 4 + (frag * 64 + off * 4) * 4,
                      &Bf[((size_t)((bn >> 3) + ntl) * 64 + ktb + ktl) * 64 + off * 4]);
        }
        cp_commit();
    };

    float acc[4][4][4] = {};
    constexpr int NS = 16;
    issue(0);
    issue(1);
    for (int s = 0; s < NS; s++) {
        if (s < NS - 1) cp_wait<1>();
        else            cp_wait<0>();
        __syncthreads();
        if (s + 2 < NS) issue(s + 2);
        const uint32_t* As = &smem[(s % 3) * 8192];
        const uint32_t* Bs = As + 4096;
#pragma unroll
        for (int ks = 0; ks < 4; ks++) {
            uint32_t af[4][4], bf[4][2];
#pragma unroll
            for (int i = 0; i < 4; i++)
                *(uint4*)af[i] = *(const uint4*)&As[((ks * 8 + wm * 4 + i) * 128) + lane * 4];
#pragma unroll
            for (int j = 0; j < 4; j++)
                *(uint2*)bf[j] = *(const uint2*)&Bs[((ks * 16 + wn * 4 + j) * 64) + lane * 2];
#pragma unroll
            for (int i = 0; i < 4; i++)
#pragma unroll
                for (int j = 0; j < 4; j++)
                    mma16(acc[i][j], af[i], bf[j]);
        }
    }

    if (EPI == 0) {
        // QKV scatter into attention fragment layouts (cols permuted [which|h|d])
        const int which = bn >> 10;
#pragma unroll
        for (int i = 0; i < 4; i++) {
#pragma unroll
            for (int j = 0; j < 4; j++) {
                int m0  = bm + (wm * 4 + i) * 16 + gid;       // rows m0, m0+8
                int b_  = m0 >> 11, t0 = m0 & (T - 1);
                int np0 = bn + (wn * 4 + j) * 8 + tig * 2;
                int h = (np0 >> 6) & 15, d0 = np0 & 63;
                const float* a = acc[i][j];
                if (which == 0) {
                    size_t fb = (((size_t)(b_ * H + h) * (T / 16) + (t0 >> 4)) * 4 +
                                 (d0 >> 4)) * 32 + lane;
                    int rb = ((d0 >> 3) & 1) * 2;
                    g_Qf[fb * 4 + rb]     = f22h(a[0] * QSCALE, a[1] * QSCALE);
                    g_Qf[fb * 4 + rb + 1] = f22h(a[2] * QSCALE, a[3] * QSCALE);
                } else if (which == 1) {
                    int rg = (d0 >> 3) & 1;
                    size_t f0 = (((size_t)(b_ * H + h) * (T / 8) + (t0 >> 3)) * 4 +
                                 (d0 >> 4)) * 32 + lane;
                    size_t f1 = (((size_t)(b_ * H + h) * (T / 8) + ((t0 + 8) >> 3)) * 4 +
                                 (d0 >> 4)) * 32 + lane;
                    g_Kf[f0 * 2 + rg] = f22h(a[0], a[1]);
                    g_Kf[f1 * 2 + rg] = f22h(a[2], a[3]);
                } else {
                    __half* Vh = (__half*)g_Vf;
#pragma unroll
                    for (int r = 0; r < 4; r++) {
                        int tt = t0 + (r >> 1) * 8;
                        int d  = d0 + (r & 1);
                        int lv = ((d & 7) << 2) | ((tt & 7) >> 1);
                        int rv = (tt & 15) >> 3;
                        size_t w = ((((size_t)(b_ * H + h) * (T / 16) + (tt >> 4)) * 8 +
                                     (d >> 3)) * 32 + lv) * 2 + rv;
                        Vh[w * 2 + (tt & 1)] = __float2half_rn(a[r]);
                    }
                }
            }
        }
    } else {
#pragma unroll
        for (int i = 0; i < 4; i++) {
#pragma unroll
            for (int j = 0; j < 4; j++) {
#pragma unroll
                for (int rh = 0; rh < 2; rh++) {
                    int m = bm + (wm * 4 + i) * 16 + gid + rh * 8;
                    int n = bn + (wn * 4 + j) * 8 + tig * 2;
                    *(float2*)&Cout[(size_t)m * E + n] =
                        make_float2(acc[i][j][rh * 2], acc[i][j][rh * 2 + 1]);
                }
            }
        }
    }
}

__global__ __launch_bounds__(256) void k_qkv() {
    gemm_core<0>(g_Xf, g_Wqf, nullptr);
}
__global__ __launch_bounds__(256) void k_out(float* __restrict__ Cout) {
    gemm_core<1>(g_AOf, g_Wof, Cout);
}

// ---------------------------------------------------------------------------
// Flash attention, no online max. BLOCK_M=128 (8 warps x 16 rows), BLOCK_N=64.
// S: f32-acc mma. NEW softmax path: S -> half2 -> h2exp2 (ex2.approx.f16x2,
// half the MUFU ops) -> result IS the PV A-frag word. Row sums via HADD2 tree
// per iteration, accumulated in f32 across iterations.
// ---------------------------------------------------------------------------
constexpr int ATTN_SMEM_BYTES = 2 * 4096 * 4;   // 32KB

__global__ __launch_bounds__(256) void k_attn() {
    extern __shared__ uint32_t sm[];
    const int tid = threadIdx.x, lane = tid & 31, warp = tid >> 5;
    const int bh = blockIdx.y;
    const int bm = blockIdx.x * 128;

    const uint32_t* __restrict__ Kfb = g_Kf + (size_t)bh * (T / 8) * 4 * 64;
    const uint32_t* __restrict__ Vfb = g_Vf + (size_t)bh * (T / 16) * 8 * 64;

    uint32_t qf[4][4];
    {
        const uint32_t* qsrc =
            g_Qf + ((size_t)bh * (T / 16) + (bm >> 4) + warp) * 4 * 128;
#pragma unroll
        for (int dt = 0; dt < 4; dt++)
            *(uint4*)qf[dt] = *(const uint4*)&qsrc[dt * 128 + lane * 4];
    }

    auto issue = [&](int s) {
        uint32_t sK = smem_u32(&sm[(s & 1) * 4096]);
        uint32_t sV = sK + 2048 * 4;
        int jb8 = s * 8, jb16 = s * 4;
#pragma unroll
        for (int it = 0; it < 2; it++) {
            int c = it * 256 + tid;
            int f = c >> 4, off = c & 15;
            cpasync16(sK + (f * 64 + off * 4) * 4,
                      &Kfb[((size_t)(jb8 + (f >> 2)) * 4 + (f & 3)) * 64 + off * 4]);
        }
#pragma unroll
        for (int it = 0; it < 2; it++) {
            int c = it * 256 + tid;
            int f = c >> 4, off = c & 15;
            cpasync16(sV + (f * 64 + off * 4) * 4,
                      &Vfb[((size_t)(jb16 + (f >> 3)) * 8 + (f & 7)) * 64 + off * 4]);
        }
        cp_commit();
    };

    float li[2] = {0.f, 0.f};
    float o[8][4] = {};

    constexpr int NS = T / 64;   // 32
    issue(0);
    for (int it = 0; it < NS; it++) {
        if (it + 1 < NS) { issue(it + 1); cp_wait<1>(); }
        else             { cp_wait<0>(); }
        __syncthreads();
        const uint32_t* Ks = &sm[(it & 1) * 4096];
        const uint32_t* Vs = Ks + 2048;

        // S = Q K^T (f32 accumulators, log2-domain scores)
        float s[8][4] = {};
#pragma unroll
        for (int dt = 0; dt < 4; dt++) {
#pragma unroll
            for (int jt = 0; jt < 8; jt++) {
                uint32_t bf[2];
                *(uint2*)bf = *(const uint2*)&Ks[((jt * 4 + dt) * 64) + lane * 2];
                mma16(s[jt], qf[dt], bf);
            }
        }

        // P = exp2(S) in half2 (MUFU halved; output IS the PV A-frag word).
        // Row sums: HADD2 accumulate per iteration, f32 across iterations.
        uint32_t pw[8][2];
        __half2 a0 = __float2half2_rn(0.f), a1 = __float2half2_rn(0.f);
#pragma unroll
        for (int jt = 0; jt < 8; jt++) {
            __half2 h0 = __floats2half2_rn(s[jt][0], s[jt][1]);
            __half2 h1 = __floats2half2_rn(s[jt][2], s[jt][3]);
            __half2 p0 = h2exp2(h0);
            __half2 p1 = h2exp2(h1);
            pw[jt][0] = *(uint32_t*)&p0;
            pw[jt][1] = *(uint32_t*)&p1;
            a0 = __hadd2(a0, p0);
            a1 = __hadd2(a1, p1);
        }
        {
            float2 f0 = __half22float2(a0), f1 = __half22float2(a1);
            li[0] += f0.x + f0.y;
            li[1] += f1.x + f1.y;
        }

        // O += P V (f32 accumulators; pf words already packed)
#pragma unroll
        for (int kt = 0; kt < 4; kt++) {
            uint32_t pf[4];
            pf[0] = pw[2 * kt][0];
            pf[1] = pw[2 * kt][1];
            pf[2] = pw[2 * kt + 1][0];
            pf[3] = pw[2 * kt + 1][1];
#pragma unroll
            for (int dn = 0; dn < 8; dn++) {
                uint32_t bf[2];
                *(uint2*)bf = *(const uint2*)&Vs[((kt * 8 + dn) * 64) + lane * 2];
                mma16(o[dn], pf, bf);
            }
        }
        __syncthreads();
    }

    // Quad-reduce row sums once
#pragma unroll
    for (int h = 0; h < 2; h++) {
        li[h] += __shfl_xor_sync(0xffffffffu, li[h], 1);
        li[h] += __shfl_xor_sync(0xffffffffu, li[h], 2);
    }
    float inv[2] = {1.f / li[0], 1.f / li[1]};

    // Epilogue: AO -> A-frags for k_out (m = b*T+t, k = h*64+d)
    const int b_ = bh >> 4, h_ = bh & 15;
    const int mt = ((b_ * T + bm) >> 4) + warp;
#pragma unroll
    for (int dn = 0; dn < 8; dn++) {
        int kt = h_ * 4 + (dn >> 1);
        int rb = (dn & 1) * 2;
        size_t fb = ((size_t)mt * 64 + kt) * 32 + lane;
        g_AOf[fb * 4 + rb]     = f22h(o[dn][0] * inv[0], o[dn][1] * inv[0]);
        g_AOf[fb * 4 + rb + 1] = f22h(o[dn][2] * inv[1], o[dn][3] * inv[1]);
    }
}

// ---------------------------------------------------------------------------
extern "C" void kernel_launch(void* const* d_in, const int* in_sizes, int n_in,
                              void* d_out, int out_size) {
    const float* x     = (const float*)d_in[0];
    const float* w_qkv = (const float*)d_in[1];
    const float* w_out = (const float*)d_in[2];
    float* out = (float*)d_out;

    cudaFuncSetAttribute(k_attn, cudaFuncAttributeMaxDynamicSharedMemorySize,
                         ATTN_SMEM_BYTES);
    cudaFuncSetAttribute(k_qkv, cudaFuncAttributeMaxDynamicSharedMemorySize,
                         GEMM_SMEM_BYTES);
    cudaFuncSetAttribute(k_out, cudaFuncAttributeMaxDynamicSharedMemorySize,
                         GEMM_SMEM_BYTES);

    k_perm<<<PERM_BLOCKS, 256>>>(x, w_qkv, w_out);
    k_qkv<<<dim3(NQKV / 128, M / 128), 256, GEMM_SMEM_BYTES>>>();
    k_attn<<<dim3(T / 128, B * H), 256, ATTN_SMEM_BYTES>>>();
    k_out<<<dim3(E / 128, M / 128), 256, GEMM_SMEM_BYTES>>>(out);
}

// round 15
// speedup vs baseline: 1.0637x; 1.0123x over previous
#include <cuda_runtime.h>
#include <cuda_fp16.h>
#include <math_constants.h>
#include <cstdint>

// Problem constants
constexpr int B  = 2;
constexpr int T  = 2048;
constexpr int E  = 1024;
constexpr int H  = 16;
constexpr int DH = 64;
constexpr int M    = B * T;        // 4096
constexpr int NQKV = 3 * H * DH;   // 3072
constexpr int HD   = H * DH;       // 1024

// Q pre-scale: DH^-0.5 * log2(e)  (attention uses exp2)
#define QSCALE 0.180336880972f

// ---------------------------------------------------------------------------
// fp16 m16n8k16 fragment layouts (PTX ISA):
// A (16x16) elem (r,c): lane=((r&7)<<2)|((c&7)>>1), reg=((c>>3)<<1)|((r>>3)&1), half=c&1
// B (16x8)  elem (k,n): lane=((n&7)<<2)|((k&7)>>1), reg=(k>>3)&1,               half=k&1
// C f32 (16x8): c0=(gid,2t) c1=(gid,2t+1) c2=(gid+8,2t) c3=(gid+8,2t+1)
// ---------------------------------------------------------------------------
__device__ uint32_t g_Xf  [(size_t)(M / 16) * (E / 16) * 128];
__device__ uint32_t g_Wqf [(size_t)(NQKV / 8) * (E / 16) * 64];
__device__ uint32_t g_Wof [(size_t)(E / 8) * (HD / 16) * 64];
__device__ uint32_t g_Qf  [(size_t)(B * H) * (T / 16) * 4 * 128];
__device__ uint32_t g_Kf  [(size_t)(B * H) * (T / 8) * 4 * 64];
__device__ uint32_t g_Vf  [(size_t)(B * H) * (T / 16) * 8 * 64];
__device__ uint32_t g_AOf [(size_t)(M / 16) * (HD / 16) * 128];

// ---------------------------------------------------------------------------
// Helpers
// ---------------------------------------------------------------------------
__device__ __forceinline__ uint32_t f22h(float a, float b) {
    __half2 h = __floats2half2_rn(a, b);
    return *(uint32_t*)&h;
}
__device__ __forceinline__ float ex2(float x) {
    float y;
    asm("ex2.approx.f32 %0, %1;" : "=f"(y) : "f"(x));
    return y;
}
__device__ __forceinline__ uint32_t smem_u32(const void* p) {
    return (uint32_t)__cvta_generic_to_shared(p);
}
__device__ __forceinline__ void cpasync16(uint32_t dst, const void* src) {
    asm volatile("cp.async.cg.shared.global [%0], [%1], 16;" :: "r"(dst), "l"(src));
}
__device__ __forceinline__ void cp_commit() { asm volatile("cp.async.commit_group;"); }
template <int N>
__device__ __forceinline__ void cp_wait() { asm volatile("cp.async.wait_group %0;" :: "n"(N)); }

__device__ __forceinline__ void mma16(float* c, const uint32_t* a, const uint32_t* b) {
    asm volatile(
        "mma.sync.aligned.m16n8k16.row.col.f32.f16.f16.f32 "
        "{%0,%1,%2,%3}, {%4,%5,%6,%7}, {%8,%9}, {%0,%1,%2,%3};"
        : "+f"(c[0]), "+f"(c[1]), "+f"(c[2]), "+f"(c[3])
        : "r"(a[0]), "r"(a[1]), "r"(a[2]), "r"(a[3]), "r"(b[0]), "r"(b[1]));
}

// ---------------------------------------------------------------------------
// Fused pre-pass (round-11, measured passing): fragment-ordered fp16 operands.
// Block ranges: [0,2048) permA | [2048,5120) permWq | [5120,6144) permWo
// ---------------------------------------------------------------------------
constexpr int PERM_A_BLOCKS  = (M / 16) * (E / 16) * 32 / 256;     // 2048
constexpr int PERM_WQ_BLOCKS = (NQKV / 8) * (E / 16) * 32 / 256;   // 3072
constexpr int PERM_WO_BLOCKS = (E / 8) * (HD / 16) * 32 / 256;     // 1024
constexpr int PERM_BLOCKS    = PERM_A_BLOCKS + PERM_WQ_BLOCKS + PERM_WO_BLOCKS;

__global__ __launch_bounds__(256) void k_perm(const float* __restrict__ X,
                                              const float* __restrict__ Wq,
                                              const float* __restrict__ Wo) {
    int blk = blockIdx.x;
    if (blk < PERM_A_BLOCKS) {
        int idx  = blk * 256 + threadIdx.x;
        int frag = idx >> 5, lane = idx & 31;
        int mt = frag >> 6, kt = frag & 63;
        int gid = lane >> 2, tp = lane & 3;
        int r0 = mt * 16 + gid, c0 = kt * 16 + tp * 2;
        float2 x00 = *(const float2*)&X[(size_t)r0 * E + c0];
        float2 x10 = *(const float2*)&X[(size_t)(r0 + 8) * E + c0];
        float2 x01 = *(const float2*)&X[(size_t)r0 * E + c0 + 8];
        float2 x11 = *(const float2*)&X[(size_t)(r0 + 8) * E + c0 + 8];
        *(uint4*)&g_Xf[(size_t)idx * 4] =
            make_uint4(f22h(x00.x, x00.y), f22h(x10.x, x10.y),
                       f22h(x01.x, x01.y), f22h(x11.x, x11.y));
    } else if (blk < PERM_A_BLOCKS + PERM_WQ_BLOCKS) {
        int idx  = (blk - PERM_A_BLOCKS) * 256 + threadIdx.x;
        int frag = idx >> 5, lane = idx & 31;
        int nt = frag >> 6, kt = frag & 63;
        int np = nt * 8 + (lane >> 2);              // permuted col [which|h|d]
        int which = np >> 10, h = (np >> 6) & 15, d = np & 63;
        int c = d * 48 + which * 16 + h;            // original col
        int k0 = kt * 16 + (lane & 3) * 2;
        uint2 v;
        v.x = f22h(Wq[(size_t)k0 * NQKV + c],       Wq[(size_t)(k0 + 1) * NQKV + c]);
        v.y = f22h(Wq[(size_t)(k0 + 8) * NQKV + c], Wq[(size_t)(k0 + 9) * NQKV + c]);
        *(uint2*)&g_Wqf[(size_t)idx * 2] = v;
    } else {
        int idx  = (blk - PERM_A_BLOCKS - PERM_WQ_BLOCKS) * 256 + threadIdx.x;
        int frag = idx >> 5, lane = idx & 31;
        int nt = frag >> 6, kt = frag & 63;
        int n = nt * 8 + (lane >> 2);
        int k0 = kt * 16 + (lane & 3) * 2;
        uint2 v;
        v.x = f22h(Wo[(size_t)k0 * E + n],       Wo[(size_t)(k0 + 1) * E + n]);
        v.y = f22h(Wo[(size_t)(k0 + 8) * E + n], Wo[(size_t)(k0 + 9) * E + n]);
        *(uint2*)&g_Wof[(size_t)idx * 2] = v;
    }
}

// ---------------------------------------------------------------------------
// GEMM core (round-7 config, best measured): 128x128 tile, 8 warps (2m x 4n),
// warp 64x32, K-stage = 64 -> 16 stages, 3-stage cp.async, plain inner loop.
// ---------------------------------------------------------------------------
constexpr int GEMM_SMEM_BYTES = 3 * 8192 * 4;   // 96KB

template <int EPI>   // 0 = QKV scatter, 1 = direct float out
__device__ __forceinline__ void gemm_core(const uint32_t* __restrict__ Af,
                                          const uint32_t* __restrict__ Bf,
                                          float* __restrict__ Cout) {
    extern __shared__ uint32_t smem[];     // [3][8192]
    const int tid = threadIdx.x, lane = tid & 31, warp = tid >> 5;
    const int wm = warp >> 2, wn = warp & 3;
    const int bm = blockIdx.y * 128, bn = blockIdx.x * 128;
    const int gid = lane >> 2, tig = lane & 3;

    auto issue = [&](int s) {
        uint32_t base = smem_u32(&smem[(s % 3) * 8192]);
        int ktb = s * 4;
#pragma unroll
        for (int it = 0; it < 4; it++) {   // A: 1024 chunks of 16B, frag=[ktl(4)][mtl(8)]
            int c = it * 256 + tid;
            int frag = c >> 5, off = c & 31;
            int mtl = frag & 7, ktl = frag >> 3;
            cpasync16(base + (frag * 128 + off * 4) * 4,
                      &Af[((size_t)((bm >> 4) + mtl) * 64 + ktb + ktl) * 128 + off * 4]);
        }
#pragma unroll
        for (int it = 0; it < 4; it++) {   // B: 1024 chunks, frag=[ktl(4)][ntl(16)]
            int c = it * 256 + tid;
            int frag = c >> 4, off = c & 15;
            int ntl = frag & 15, ktl = frag >> 4;
            cpasync16(base + 4096 * 4 + (frag * 64 + off * 4) * 4,
                      &Bf[((size_t)((bn >> 3) + ntl) * 64 + ktb + ktl) * 64 + off * 4]);
        }
        cp_commit();
    };

    float acc[4][4][4] = {};
    constexpr int NS = 16;
    issue(0);
    issue(1);
    for (int s = 0; s < NS; s++) {
        if (s < NS - 1) cp_wait<1>();
        else            cp_wait<0>();
        __syncthreads();
        if (s + 2 < NS) issue(s + 2);
        const uint32_t* As = &smem[(s % 3) * 8192];
        const uint32_t* Bs = As + 4096;
#pragma unroll
        for (int ks = 0; ks < 4; ks++) {
            uint32_t af[4][4], bf[4][2];
#pragma unroll
            for (int i = 0; i < 4; i++)
                *(uint4*)af[i] = *(const uint4*)&As[((ks * 8 + wm * 4 + i) * 128) + lane * 4];
#pragma unroll
            for (int j = 0; j < 4; j++)
                *(uint2*)bf[j] = *(const uint2*)&Bs[((ks * 16 + wn * 4 + j) * 64) + lane * 2];
#pragma unroll
            for (int i = 0; i < 4; i++)
#pragma unroll
                for (int j = 0; j < 4; j++)
                    mma16(acc[i][j], af[i], bf[j]);
        }
    }

    if (EPI == 0) {
        // QKV scatter into attention fragment layouts (cols permuted [which|h|d])
        const int which = bn >> 10;
#pragma unroll
        for (int i = 0; i < 4; i++) {
#pragma unroll
            for (int j = 0; j < 4; j++) {
                int m0  = bm + (wm * 4 + i) * 16 + gid;       // rows m0, m0+8
                int b_  = m0 >> 11, t0 = m0 & (T - 1);
                int np0 = bn + (wn * 4 + j) * 8 + tig * 2;
                int h = (np0 >> 6) & 15, d0 = np0 & 63;
                const float* a = acc[i][j];
                if (which == 0) {
                    size_t fb = (((size_t)(b_ * H + h) * (T / 16) + (t0 >> 4)) * 4 +
                                 (d0 >> 4)) * 32 + lane;
                    int rb = ((d0 >> 3) & 1) * 2;
                    g_Qf[fb * 4 + rb]     = f22h(a[0] * QSCALE, a[1] * QSCALE);
                    g_Qf[fb * 4 + rb + 1] = f22h(a[2] * QSCALE, a[3] * QSCALE);
                } else if (which == 1) {
                    int rg = (d0 >> 3) & 1;
                    size_t f0 = (((size_t)(b_ * H + h) * (T / 8) + (t0 >> 3)) * 4 +
                                 (d0 >> 4)) * 32 + lane;
                    size_t f1 = (((size_t)(b_ * H + h) * (T / 8) + ((t0 + 8) >> 3)) * 4 +
                                 (d0 >> 4)) * 32 + lane;
                    g_Kf[f0 * 2 + rg] = f22h(a[0], a[1]);
                    g_Kf[f1 * 2 + rg] = f22h(a[2], a[3]);
                } else {
                    __half* Vh = (__half*)g_Vf;
#pragma unroll
                    for (int r = 0; r < 4; r++) {
                        int tt = t0 + (r >> 1) * 8;
                        int d  = d0 + (r & 1);
                        int lv = ((d & 7) << 2) | ((tt & 7) >> 1);
                        int rv = (tt & 15) >> 3;
                        size_t w = ((((size_t)(b_ * H + h) * (T / 16) + (tt >> 4)) * 8 +
                                     (d >> 3)) * 32 + lv) * 2 + rv;
                        Vh[w * 2 + (tt & 1)] = __float2half_rn(a[r]);
                    }
                }
            }
        }
    } else {
#pragma unroll
        for (int i = 0; i < 4; i++) {
#pragma unroll
            for (int j = 0; j < 4; j++) {
#pragma unroll
                for (int rh = 0; rh < 2; rh++) {
                    int m = bm + (wm * 4 + i) * 16 + gid + rh * 8;
                    int n = bn + (wn * 4 + j) * 8 + tig * 2;
                    *(float2*)&Cout[(size_t)m * E + n] =
                        make_float2(acc[i][j][rh * 2], acc[i][j][rh * 2 + 1]);
                }
            }
        }
    }
}

__global__ __launch_bounds__(256) void k_qkv() {
    gemm_core<0>(g_Xf, g_Wqf, nullptr);
}
__global__ __launch_bounds__(256) void k_out(float* __restrict__ Cout) {
    gemm_core<1>(g_AOf, g_Wof, Cout);
}

// ---------------------------------------------------------------------------
// Flash attention, no online max. BLOCK_M=128 (8 warps x 16 rows), BLOCK_N=64.
// f32 ex2 softmax (best measured accuracy). NEW: 3-stage cp.async K/V pipeline
// (48KB smem) so each stage's load latency is covered by two compute iters.
// ---------------------------------------------------------------------------
constexpr int ATTN_SMEM_BYTES = 3 * 4096 * 4;   // 48KB

__global__ __launch_bounds__(256) void k_attn() {
    extern __shared__ uint32_t sm[];
    const int tid = threadIdx.x, lane = tid & 31, warp = tid >> 5;
    const int bh = blockIdx.y;
    const int bm = blockIdx.x * 128;

    const uint32_t* __restrict__ Kfb = g_Kf + (size_t)bh * (T / 8) * 4 * 64;
    const uint32_t* __restrict__ Vfb = g_Vf + (size_t)bh * (T / 16) * 8 * 64;

    uint32_t qf[4][4];
    {
        const uint32_t* qsrc =
            g_Qf + ((size_t)bh * (T / 16) + (bm >> 4) + warp) * 4 * 128;
#pragma unroll
        for (int dt = 0; dt < 4; dt++)
            *(uint4*)qf[dt] = *(const uint4*)&qsrc[dt * 128 + lane * 4];
    }

    auto issue = [&](int s) {
        uint32_t sK = smem_u32(&sm[(s % 3) * 4096]);
        uint32_t sV = sK + 2048 * 4;
        int jb8 = s * 8, jb16 = s * 4;
#pragma unroll
        for (int it = 0; it < 2; it++) {
            int c = it * 256 + tid;
            int f = c >> 4, off = c & 15;
            cpasync16(sK + (f * 64 + off * 4) * 4,
                      &Kfb[((size_t)(jb8 + (f >> 2)) * 4 + (f & 3)) * 64 + off * 4]);
        }
#pragma unroll
        for (int it = 0; it < 2; it++) {
            int c = it * 256 + tid;
            int f = c >> 4, off = c & 15;
            cpasync16(sV + (f * 64 + off * 4) * 4,
                      &Vfb[((size_t)(jb16 + (f >> 3)) * 8 + (f & 7)) * 64 + off * 4]);
        }
        cp_commit();
    };

    float li[2] = {0.f, 0.f};
    float o[8][4] = {};

    constexpr int NS = T / 64;   // 32
    issue(0);
    issue(1);
    for (int it = 0; it < NS; it++) {
        if (it < NS - 1) cp_wait<1>();
        else             cp_wait<0>();
        __syncthreads();
        if (it + 2 < NS) issue(it + 2);
        const uint32_t* Ks = &sm[(it % 3) * 4096];
        const uint32_t* Vs = Ks + 2048;

        // S = Q K^T (f32 accumulators, log2-domain scores)
        float s[8][4] = {};
#pragma unroll
        for (int dt = 0; dt < 4; dt++) {
#pragma unroll
            for (int jt = 0; jt < 8; jt++) {
                uint32_t bf[2];
                *(uint2*)bf = *(const uint2*)&Ks[((jt * 4 + dt) * 64) + lane * 2];
                mma16(s[jt], qf[dt], bf);
            }
        }

        // P = exp2(S), accumulate row sums
#pragma unroll
        for (int jt = 0; jt < 8; jt++) {
#pragma unroll
            for (int r = 0; r < 4; r++)
                s[jt][r] = ex2(s[jt][r]);
            li[0] += s[jt][0] + s[jt][1];
            li[1] += s[jt][2] + s[jt][3];
        }

        // O += P V (P C-frag -> A-frag in registers; lane map is identity)
#pragma unroll
        for (int kt = 0; kt < 4; kt++) {
            uint32_t pf[4];
            pf[0] = f22h(s[2 * kt][0],     s[2 * kt][1]);
            pf[1] = f22h(s[2 * kt][2],     s[2 * kt][3]);
            pf[2] = f22h(s[2 * kt + 1][0], s[2 * kt + 1][1]);
            pf[3] = f22h(s[2 * kt + 1][2], s[2 * kt + 1][3]);
#pragma unroll
            for (int dn = 0; dn < 8; dn++) {
                uint32_t bf[2];
                *(uint2*)bf = *(const uint2*)&Vs[((kt * 8 + dn) * 64) + lane * 2];
                mma16(o[dn], pf, bf);
            }
        }
    }

    // Quad-reduce row sums once
#pragma unroll
    for (int h = 0; h < 2; h++) {
        li[h] += __shfl_xor_sync(0xffffffffu, li[h], 1);
        li[h] += __shfl_xor_sync(0xffffffffu, li[h], 2);
    }
    float inv[2] = {1.f / li[0], 1.f / li[1]};

    // Epilogue: AO -> A-frags for k_out (m = b*T+t, k = h*64+d)
    const int b_ = bh >> 4, h_ = bh & 15;
    const int mt = ((b_ * T + bm) >> 4) + warp;
#pragma unroll
    for (int dn = 0; dn < 8; dn++) {
        int kt = h_ * 4 + (dn >> 1);
        int rb = (dn & 1) * 2;
        size_t fb = ((size_t)mt * 64 + kt) * 32 + lane;
        g_AOf[fb * 4 + rb]     = f22h(o[dn][0] * inv[0], o[dn][1] * inv[0]);
        g_AOf[fb * 4 + rb + 1] = f22h(o[dn][2] * inv[1], o[dn][3] * inv[1]);
    }
}

// ---------------------------------------------------------------------------
extern "C" void kernel_launch(void* const* d_in, const int* in_sizes, int n_in,
                              void* d_out, int out_size) {
    const float* x     = (const float*)d_in[0];
    const float* w_qkv = (const float*)d_in[1];
    const float* w_out = (const float*)d_in[2];
    float* out = (float*)d_out;

    cudaFuncSetAttribute(k_attn, cudaFuncAttributeMaxDynamicSharedMemorySize,
                         ATTN_SMEM_BYTES);
    cudaFuncSetAttribute(k_qkv, cudaFuncAttributeMaxDynamicSharedMemorySize,
                         GEMM_SMEM_BYTES);
    cudaFuncSetAttribute(k_out, cudaFuncAttributeMaxDynamicSharedMemorySize,
                         GEMM_SMEM_BYTES);

    k_perm<<<PERM_BLOCKS, 256>>>(x, w_qkv, w_out);
    k_qkv<<<dim3(NQKV / 128, M / 128), 256, GEMM_SMEM_BYTES>>>();
    k_attn<<<dim3(T / 128, B * H), 256, ATTN_SMEM_BYTES>>>();
    k_out<<<dim3(E / 128, M / 128), 256, GEMM_SMEM_BYTES>>>(out);
}

// round 16
// speedup vs baseline: 1.0780x; 1.0134x over previous
#include <cuda_runtime.h>
#include <cuda_fp16.h>
#include <math_constants.h>
#include <cstdint>

// Problem constants
constexpr int B  = 2;
constexpr int T  = 2048;
constexpr int E  = 1024;
constexpr int H  = 16;
constexpr int DH = 64;
constexpr int M    = B * T;        // 4096
constexpr int NQKV = 3 * H * DH;   // 3072
constexpr int HD   = H * DH;       // 1024

// Q pre-scale: DH^-0.5 * log2(e)  (attention uses exp2)
#define QSCALE 0.180336880972f

// ---------------------------------------------------------------------------
// fp16 m16n8k16 fragment layouts (PTX ISA):
// A (16x16) elem (r,c): lane=((r&7)<<2)|((c&7)>>1), reg=((c>>3)<<1)|((r>>3)&1), half=c&1
// B (16x8)  elem (k,n): lane=((n&7)<<2)|((k&7)>>1), reg=(k>>3)&1,               half=k&1
// C f32 (16x8): c0=(gid,2t) c1=(gid,2t+1) c2=(gid+8,2t) c3=(gid+8,2t+1)
// ---------------------------------------------------------------------------
__device__ uint32_t g_Xf  [(size_t)(M / 16) * (E / 16) * 128];
__device__ uint32_t g_Wqf [(size_t)(NQKV / 8) * (E / 16) * 64];
__device__ uint32_t g_Wof [(size_t)(E / 8) * (HD / 16) * 64];
__device__ uint32_t g_Qf  [(size_t)(B * H) * (T / 16) * 4 * 128];
__device__ uint32_t g_Kf  [(size_t)(B * H) * (T / 8) * 4 * 64];
__device__ uint32_t g_Vf  [(size_t)(B * H) * (T / 16) * 8 * 64];
__device__ uint32_t g_AOf [(size_t)(M / 16) * (HD / 16) * 128];

// ---------------------------------------------------------------------------
// Helpers
// ---------------------------------------------------------------------------
__device__ __forceinline__ uint32_t f22h(float a, float b) {
    __half2 h = __floats2half2_rn(a, b);
    return *(uint32_t*)&h;
}
__device__ __forceinline__ float ex2(float x) {
    float y;
    asm("ex2.approx.f32 %0, %1;" : "=f"(y) : "f"(x));
    return y;
}
__device__ __forceinline__ uint32_t smem_u32(const void* p) {
    return (uint32_t)__cvta_generic_to_shared(p);
}
__device__ __forceinline__ void cpasync16(uint32_t dst, const void* src) {
    asm volatile("cp.async.cg.shared.global [%0], [%1], 16;" :: "r"(dst), "l"(src));
}
__device__ __forceinline__ void cp_commit() { asm volatile("cp.async.commit_group;"); }
template <int N>
__device__ __forceinline__ void cp_wait() { asm volatile("cp.async.wait_group %0;" :: "n"(N)); }

__device__ __forceinline__ void mma16(float* c, const uint32_t* a, const uint32_t* b) {
    asm volatile(
        "mma.sync.aligned.m16n8k16.row.col.f32.f16.f16.f32 "
        "{%0,%1,%2,%3}, {%4,%5,%6,%7}, {%8,%9}, {%0,%1,%2,%3};"
        : "+f"(c[0]), "+f"(c[1]), "+f"(c[2]), "+f"(c[3])
        : "r"(a[0]), "r"(a[1]), "r"(a[2]), "r"(a[3]), "r"(b[0]), "r"(b[1]));
}

// ---------------------------------------------------------------------------
// Fused pre-pass (round-11, measured passing): fragment-ordered fp16 operands.
// Block ranges: [0,2048) permA | [2048,5120) permWq | [5120,6144) permWo
// ---------------------------------------------------------------------------
constexpr int PERM_A_BLOCKS  = (M / 16) * (E / 16) * 32 / 256;     // 2048
constexpr int PERM_WQ_BLOCKS = (NQKV / 8) * (E / 16) * 32 / 256;   // 3072
constexpr int PERM_WO_BLOCKS = (E / 8) * (HD / 16) * 32 / 256;     // 1024
constexpr int PERM_BLOCKS    = PERM_A_BLOCKS + PERM_WQ_BLOCKS + PERM_WO_BLOCKS;

__global__ __launch_bounds__(256) void k_perm(const float* __restrict__ X,
                                              const float* __restrict__ Wq,
                                              const float* __restrict__ Wo) {
    int blk = blockIdx.x;
    if (blk < PERM_A_BLOCKS) {
        int idx  = blk * 256 + threadIdx.x;
        int frag = idx >> 5, lane = idx & 31;
        int mt = frag >> 6, kt = frag & 63;
        int gid = lane >> 2, tp = lane & 3;
        int r0 = mt * 16 + gid, c0 = kt * 16 + tp * 2;
        float2 x00 = *(const float2*)&X[(size_t)r0 * E + c0];
        float2 x10 = *(const float2*)&X[(size_t)(r0 + 8) * E + c0];
        float2 x01 = *(const float2*)&X[(size_t)r0 * E + c0 + 8];
        float2 x11 = *(const float2*)&X[(size_t)(r0 + 8) * E + c0 + 8];
        *(uint4*)&g_Xf[(size_t)idx * 4] =
            make_uint4(f22h(x00.x, x00.y), f22h(x10.x, x10.y),
                       f22h(x01.x, x01.y), f22h(x11.x, x11.y));
    } else if (blk < PERM_A_BLOCKS + PERM_WQ_BLOCKS) {
        int idx  = (blk - PERM_A_BLOCKS) * 256 + threadIdx.x;
        int frag = idx >> 5, lane = idx & 31;
        int nt = frag >> 6, kt = frag & 63;
        int np = nt * 8 + (lane >> 2);              // permuted col [which|h|d]
        int which = np >> 10, h = (np >> 6) & 15, d = np & 63;
        int c = d * 48 + which * 16 + h;            // original col
        int k0 = kt * 16 + (lane & 3) * 2;
        uint2 v;
        v.x = f22h(Wq[(size_t)k0 * NQKV + c],       Wq[(size_t)(k0 + 1) * NQKV + c]);
        v.y = f22h(Wq[(size_t)(k0 + 8) * NQKV + c], Wq[(size_t)(k0 + 9) * NQKV + c]);
        *(uint2*)&g_Wqf[(size_t)idx * 2] = v;
    } else {
        int idx  = (blk - PERM_A_BLOCKS - PERM_WQ_BLOCKS) * 256 + threadIdx.x;
        int frag = idx >> 5, lane = idx & 31;
        int nt = frag >> 6, kt = frag & 63;
        int n = nt * 8 + (lane >> 2);
        int k0 = kt * 16 + (lane & 3) * 2;
        uint2 v;
        v.x = f22h(Wo[(size_t)k0 * E + n],       Wo[(size_t)(k0 + 1) * E + n]);
        v.y = f22h(Wo[(size_t)(k0 + 8) * E + n], Wo[(size_t)(k0 + 9) * E + n]);
        *(uint2*)&g_Wof[(size_t)idx * 2] = v;
    }
}

// ---------------------------------------------------------------------------
// GEMM core (round-7 config, best measured): 128x128 tile, 8 warps (2m x 4n),
// warp 64x32, K-stage = 64 -> 16 stages, 3-stage cp.async, plain inner loop.
// ---------------------------------------------------------------------------
constexpr int GEMM_SMEM_BYTES = 3 * 8192 * 4;   // 96KB

template <int EPI>   // 0 = QKV scatter, 1 = direct float out
__device__ __forceinline__ void gemm_core(const uint32_t* __restrict__ Af,
                                          const uint32_t* __restrict__ Bf,
                                          float* __restrict__ Cout) {
    extern __shared__ uint32_t smem[];     // [3][8192]
    const int tid = threadIdx.x, lane = tid & 31, warp = tid >> 5;
    const int wm = warp >> 2, wn = warp & 3;
    const int bm = blockIdx.y * 128, bn = blockIdx.x * 128;
    const int gid = lane >> 2, tig = lane & 3;

    auto issue = [&](int s) {
        uint32_t base = smem_u32(&smem[(s % 3) * 8192]);
        int ktb = s * 4;
#pragma unroll
        for (int it = 0; it < 4; it++) {   // A: 1024 chunks of 16B, frag=[ktl(4)][mtl(8)]
            int c = it * 256 + tid;
            int frag = c >> 5, off = c & 31;
            int mtl = frag & 7, ktl = frag >> 3;
            cpasync16(base + (frag * 128 + off * 4) * 4,
                      &Af[((size_t)((bm >> 4) + mtl) * 64 + ktb + ktl) * 128 + off * 4]);
        }
#pragma unroll
        for (int it = 0; it < 4; it++) {   // B: 1024 chunks, frag=[ktl(4)][ntl(16)]
            int c = it * 256 + tid;
            int frag = c >> 4, off = c & 15;
            int ntl = frag & 15, ktl = frag >> 4;
            cpasync16(base + 4096 * 4 + (frag * 64 + off * 4) * 4,
                      &Bf[((size_t)((bn >> 3) + ntl) * 64 + ktb + ktl) * 64 + off * 4]);
        }
        cp_commit();
    };

    float acc[4][4][4] = {};
    constexpr int NS = 16;
    issue(0);
    issue(1);
    for (int s = 0; s < NS; s++) {
        if (s < NS - 1) cp_wait<1>();
        else            cp_wait<0>();
        __syncthreads();
        if (s + 2 < NS) issue(s + 2);
        const uint32_t* As = &smem[(s % 3) * 8192];
        const uint32_t* Bs = As + 4096;
#pragma unroll
        for (int ks = 0; ks < 4; ks++) {
            uint32_t af[4][4], bf[4][2];
#pragma unroll
            for (int i = 0; i < 4; i++)
                *(uint4*)af[i] = *(const uint4*)&As[((ks * 8 + wm * 4 + i) * 128) + lane * 4];
#pragma unroll
            for (int j = 0; j < 4; j++)
                *(uint2*)bf[j] = *(const uint2*)&Bs[((ks * 16 + wn * 4 + j) * 64) + lane * 2];
#pragma unroll
            for (int i = 0; i < 4; i++)
#pragma unroll
                for (int j = 0; j < 4; j++)
                    mma16(acc[i][j], af[i], bf[j]);
        }
    }

    if (EPI == 0) {
        // QKV scatter into attention fragment layouts (cols permuted [which|h|d])
        const int which = bn >> 10;
#pragma unroll
        for (int i = 0; i < 4; i++) {
#pragma unroll
            for (int j = 0; j < 4; j++) {
                int m0  = bm + (wm * 4 + i) * 16 + gid;       // rows m0, m0+8
                int b_  = m0 >> 11, t0 = m0 & (T - 1);
                int np0 = bn + (wn * 4 + j) * 8 + tig * 2;
                int h = (np0 >> 6) & 15, d0 = np0 & 63;
                const float* a = acc[i][j];
                if (which == 0) {
                    size_t fb = (((size_t)(b_ * H + h) * (T / 16) + (t0 >> 4)) * 4 +
                                 (d0 >> 4)) * 32 + lane;
                    int rb = ((d0 >> 3) & 1) * 2;
                    g_Qf[fb * 4 + rb]     = f22h(a[0] * QSCALE, a[1] * QSCALE);
                    g_Qf[fb * 4 + rb + 1] = f22h(a[2] * QSCALE, a[3] * QSCALE);
                } else if (which == 1) {
                    int rg = (d0 >> 3) & 1;
                    size_t f0 = (((size_t)(b_ * H + h) * (T / 8) + (t0 >> 3)) * 4 +
                                 (d0 >> 4)) * 32 + lane;
                    size_t f1 = (((size_t)(b_ * H + h) * (T / 8) + ((t0 + 8) >> 3)) * 4 +
                                 (d0 >> 4)) * 32 + lane;
                    g_Kf[f0 * 2 + rg] = f22h(a[0], a[1]);
                    g_Kf[f1 * 2 + rg] = f22h(a[2], a[3]);
                } else {
                    __half* Vh = (__half*)g_Vf;
#pragma unroll
                    for (int r = 0; r < 4; r++) {
                        int tt = t0 + (r >> 1) * 8;
                        int d  = d0 + (r & 1);
                        int lv = ((d & 7) << 2) | ((tt & 7) >> 1);
                        int rv = (tt & 15) >> 3;
                        size_t w = ((((size_t)(b_ * H + h) * (T / 16) + (tt >> 4)) * 8 +
                                     (d >> 3)) * 32 + lv) * 2 + rv;
                        Vh[w * 2 + (tt & 1)] = __float2half_rn(a[r]);
                    }
                }
            }
        }
    } else {
#pragma unroll
        for (int i = 0; i < 4; i++) {
#pragma unroll
            for (int j = 0; j < 4; j++) {
#pragma unroll
                for (int rh = 0; rh < 2; rh++) {
                    int m = bm + (wm * 4 + i) * 16 + gid + rh * 8;
                    int n = bn + (wn * 4 + j) * 8 + tig * 2;
                    *(float2*)&Cout[(size_t)m * E + n] =
                        make_float2(acc[i][j][rh * 2], acc[i][j][rh * 2 + 1]);
                }
            }
        }
    }
}

__global__ __launch_bounds__(256) void k_qkv() {
    gemm_core<0>(g_Xf, g_Wqf, nullptr);
}
__global__ __launch_bounds__(256) void k_out(float* __restrict__ Cout) {
    gemm_core<1>(g_AOf, g_Wof, Cout);
}

// ---------------------------------------------------------------------------
// Flash attention, no online max. BLOCK_M=128 (8 warps x 16 rows).
// NEW: 128 keys staged per pipeline step (stage = K 16KB + V 16KB = 32KB,
// 3 stages = 96KB, still 2 CTAs/SM). Compute proceeds in two 64-key halves
// reusing the same registers, so per-iter fixed costs (waits/barriers) halve.
// ---------------------------------------------------------------------------
constexpr int ATTN_SMEM_BYTES = 3 * 8192 * 4;   // 96KB

__global__ __launch_bounds__(256) void k_attn() {
    extern __shared__ uint32_t sm[];
    const int tid = threadIdx.x, lane = tid & 31, warp = tid >> 5;
    const int bh = blockIdx.y;
    const int bm = blockIdx.x * 128;

    const uint32_t* __restrict__ Kfb = g_Kf + (size_t)bh * (T / 8) * 4 * 64;
    const uint32_t* __restrict__ Vfb = g_Vf + (size_t)bh * (T / 16) * 8 * 64;

    uint32_t qf[4][4];
    {
        const uint32_t* qsrc =
            g_Qf + ((size_t)bh * (T / 16) + (bm >> 4) + warp) * 4 * 128;
#pragma unroll
        for (int dt = 0; dt < 4; dt++)
            *(uint4*)qf[dt] = *(const uint4*)&qsrc[dt * 128 + lane * 4];
    }

    // Stage s covers keys [s*128, (s+1)*128).
    // K: 16 j8-tiles x 4 dt = 64 frags x 256B = 16KB (1024 x 16B chunks)
    // V:  8 j16-tiles x 8 dn = 64 frags x 256B = 16KB
    auto issue = [&](int s) {
        uint32_t sK = smem_u32(&sm[(s % 3) * 8192]);
        uint32_t sV = sK + 4096 * 4;
        int jb8 = s * 16, jb16 = s * 8;
#pragma unroll
        for (int it = 0; it < 4; it++) {   // K chunks
            int c = it * 256 + tid;
            int f = c >> 4, off = c & 15;
            cpasync16(sK + (f * 64 + off * 4) * 4,
                      &Kfb[((size_t)(jb8 + (f >> 2)) * 4 + (f & 3)) * 64 + off * 4]);
        }
#pragma unroll
        for (int it = 0; it < 4; it++) {   // V chunks
            int c = it * 256 + tid;
            int f = c >> 4, off = c & 15;
            cpasync16(sV + (f * 64 + off * 4) * 4,
                      &Vfb[((size_t)(jb16 + (f >> 3)) * 8 + (f & 7)) * 64 + off * 4]);
        }
        cp_commit();
    };

    float li[2] = {0.f, 0.f};
    float o[8][4] = {};

    constexpr int NS = T / 128;   // 16
    issue(0);
    issue(1);
    for (int it = 0; it < NS; it++) {
        if (it < NS - 1) cp_wait<1>();
        else             cp_wait<0>();
        __syncthreads();
        if (it + 2 < NS) issue(it + 2);
        const uint32_t* Ks = &sm[(it % 3) * 8192];
        const uint32_t* Vs = Ks + 4096;

        // Two 64-key halves, reusing the same s[] registers
#pragma unroll
        for (int hk = 0; hk < 2; hk++) {
            // S = Q K^T (f32 accumulators, log2-domain scores)
            float s[8][4] = {};
#pragma unroll
            for (int dt = 0; dt < 4; dt++) {
#pragma unroll
                for (int jt = 0; jt < 8; jt++) {
                    uint32_t bf[2];
                    *(uint2*)bf =
                        *(const uint2*)&Ks[(((hk * 8 + jt) * 4 + dt) * 64) + lane * 2];
                    mma16(s[jt], qf[dt], bf);
                }
            }

            // P = exp2(S), accumulate row sums
#pragma unroll
            for (int jt = 0; jt < 8; jt++) {
#pragma unroll
                for (int r = 0; r < 4; r++)
                    s[jt][r] = ex2(s[jt][r]);
                li[0] += s[jt][0] + s[jt][1];
                li[1] += s[jt][2] + s[jt][3];
            }

            // O += P V (P C-frag -> A-frag in registers; lane map is identity)
#pragma unroll
            for (int kt = 0; kt < 4; kt++) {
                uint32_t pf[4];
                pf[0] = f22h(s[2 * kt][0],     s[2 * kt][1]);
                pf[1] = f22h(s[2 * kt][2],     s[2 * kt][3]);
                pf[2] = f22h(s[2 * kt + 1][0], s[2 * kt + 1][1]);
                pf[3] = f22h(s[2 * kt + 1][2], s[2 * kt + 1][3]);
#pragma unroll
                for (int dn = 0; dn < 8; dn++) {
                    uint32_t bf[2];
                    *(uint2*)bf =
                        *(const uint2*)&Vs[(((hk * 4 + kt) * 8 + dn) * 64) + lane * 2];
                    mma16(o[dn], pf, bf);
                }
            }
        }
    }

    // Quad-reduce row sums once
#pragma unroll
    for (int h = 0; h < 2; h++) {
        li[h] += __shfl_xor_sync(0xffffffffu, li[h], 1);
        li[h] += __shfl_xor_sync(0xffffffffu, li[h], 2);
    }
    float inv[2] = {1.f / li[0], 1.f / li[1]};

    // Epilogue: AO -> A-frags for k_out (m = b*T+t, k = h*64+d)
    const int b_ = bh >> 4, h_ = bh & 15;
    const int mt = ((b_ * T + bm) >> 4) + warp;
#pragma unroll
    for (int dn = 0; dn < 8; dn++) {
        int kt = h_ * 4 + (dn >> 1);
        int rb = (dn & 1) * 2;
        size_t fb = ((size_t)mt * 64 + kt) * 32 + lane;
        g_AOf[fb * 4 + rb]     = f22h(o[dn][0] * inv[0], o[dn][1] * inv[0]);
        g_AOf[fb * 4 + rb + 1] = f22h(o[dn][2] * inv[1], o[dn][3] * inv[1]);
    }
}

// ---------------------------------------------------------------------------
extern "C" void kernel_launch(void* const* d_in, const int* in_sizes, int n_in,
                              void* d_out, int out_size) {
    const float* x     = (const float*)d_in[0];
    const float* w_qkv = (const float*)d_in[1];
    const float* w_out = (const float*)d_in[2];
    float* out = (float*)d_out;

    cudaFuncSetAttribute(k_attn, cudaFuncAttributeMaxDynamicSharedMemorySize,
                         ATTN_SMEM_BYTES);
    cudaFuncSetAttribute(k_qkv, cudaFuncAttributeMaxDynamicSharedMemorySize,
                         GEMM_SMEM_BYTES);
    cudaFuncSetAttribute(k_out, cudaFuncAttributeMaxDynamicSharedMemorySize,
                         GEMM_SMEM_BYTES);

    k_perm<<<PERM_BLOCKS, 256>>>(x, w_qkv, w_out);
    k_qkv<<<dim3(NQKV / 128, M / 128), 256, GEMM_SMEM_BYTES>>>();
    k_attn<<<dim3(T / 128, B * H), 256, ATTN_SMEM_BYTES>>>();
    k_out<<<dim3(E / 128, M / 128), 256, GEMM_SMEM_BYTES>>>(out);
}